// round 9
// baseline (speedup 1.0000x reference)
#include <cuda_runtime.h>
#include <cuda_bf16.h>
#include <cuda_fp16.h>
#include <math.h>
#include <stdint.h>

// Problem constants
#define NTOK  43520        // B * LQ
#define LQ_   21760
#define C_    256
#define NHEAD_ 8
#define FF_   1024
#define NL_   6

// ---------------------------------------------------------------------------
// Scratch (static device allocations; no cudaMalloc anywhere)
// Activations stored as split bf16 hi/lo plane pairs (fp32-equivalent).
// ---------------------------------------------------------------------------
__device__ __align__(16) __nv_bfloat16 g_xpH[NTOK * C_], g_xpL[NTOK * C_];
__device__ __align__(16) __nv_bfloat16 g_xH [NTOK * C_], g_xL [NTOK * C_];
__device__ __align__(16) __nv_bfloat16 g_aoH[NTOK * C_], g_aoL[NTOK * C_];
__device__ __align__(16) __nv_bfloat16 g_hH [NTOK * FF_], g_hL [NTOK * FF_];
__device__ float  g_tmp[NTOK * C_];
__device__ __half g_vh [NTOK * C_];        // value proj, fp16 (gather source)
__device__ float  g_oa [NTOK * 384];       // off (256) + att logits (128), fused

// pre-split weights, all layers: [N,K] bf16 hi/lo
__device__ __align__(16) __nv_bfloat16 g_wcat_h[NL_ * 640 * 256];
__device__ __align__(16) __nv_bfloat16 g_wcat_l[NL_ * 640 * 256];
__device__ __align__(16) __nv_bfloat16 g_wo_h  [NL_ * 256 * 256];
__device__ __align__(16) __nv_bfloat16 g_wo_l  [NL_ * 256 * 256];
__device__ __align__(16) __nv_bfloat16 g_w1_h  [NL_ * 1024 * 256];
__device__ __align__(16) __nv_bfloat16 g_w1_l  [NL_ * 1024 * 256];
__device__ __align__(16) __nv_bfloat16 g_w2_h  [NL_ * 256 * 1024];
__device__ __align__(16) __nv_bfloat16 g_w2_l  [NL_ * 256 * 1024];
__device__ float g_bcat[NL_ * 640];

// ---------------------------------------------------------------------------
// PTX helpers (sm_103 base target)
// ---------------------------------------------------------------------------
__device__ __forceinline__ uint32_t smem_u32(const void* p) {
    return (uint32_t)__cvta_generic_to_shared(p);
}
__device__ __forceinline__ void cp_async16(uint32_t saddr, const void* gaddr) {
    asm volatile("cp.async.cg.shared.global [%0], [%1], 16;" :: "r"(saddr), "l"(gaddr));
}
__device__ __forceinline__ void cp_commit() {
    asm volatile("cp.async.commit_group;" ::: "memory");
}
__device__ __forceinline__ void cp_wait0() {
    asm volatile("cp.async.wait_group 0;" ::: "memory");
}
__device__ __forceinline__ void ldsm4(uint32_t* r, uint32_t a) {
    asm volatile("ldmatrix.sync.aligned.m8n8.x4.shared.b16 {%0,%1,%2,%3}, [%4];"
                 : "=r"(r[0]), "=r"(r[1]), "=r"(r[2]), "=r"(r[3]) : "r"(a));
}
__device__ __forceinline__ void mma16816(float* c, const uint32_t* a, const uint32_t* b) {
    asm volatile("mma.sync.aligned.m16n8k16.row.col.f32.bf16.bf16.f32 "
                 "{%0,%1,%2,%3}, {%4,%5,%6,%7}, {%8,%9}, {%0,%1,%2,%3};"
                 : "+f"(c[0]), "+f"(c[1]), "+f"(c[2]), "+f"(c[3])
                 : "r"(a[0]), "r"(a[1]), "r"(a[2]), "r"(a[3]), "r"(b[0]), "r"(b[1]));
}
__device__ __forceinline__ void split2(float v, __nv_bfloat16& h, __nv_bfloat16& l) {
    h = __float2bfloat16(v);
    l = __float2bfloat16(v - __bfloat162float(h));
}

// ---------------------------------------------------------------------------
// Weight prep: W fp32 [K,N] slice -> Bt_hi/Bt_lo bf16 [N,K] (transpose + split)
// ---------------------------------------------------------------------------
__global__ void prep_w(const float* __restrict__ W, __nv_bfloat16* __restrict__ Bh,
                       __nv_bfloat16* __restrict__ Bl, int K, int N,
                       size_t srcLayerStride, size_t dstLayerStride) {
    const int L = blockIdx.z;
    W  += (size_t)L * srcLayerStride;
    Bh += (size_t)L * dstLayerStride;
    Bl += (size_t)L * dstLayerStride;
    __shared__ float t[32][33];
    int k0 = blockIdx.y * 32, n0 = blockIdx.x * 32;
    for (int i = threadIdx.y; i < 32; i += 8)
        t[i][threadIdx.x] = W[(size_t)(k0 + i) * N + n0 + threadIdx.x];
    __syncthreads();
    for (int i = threadIdx.y; i < 32; i += 8) {
        float x = t[threadIdx.x][i];
        __nv_bfloat16 h, l;
        split2(x, h, l);
        size_t o = (size_t)(n0 + i) * K + k0 + threadIdx.x;
        Bh[o] = h;
        Bl[o] = l;
    }
}

__global__ void bias_cat(const float* __restrict__ bv, const float* __restrict__ boff,
                         const float* __restrict__ bat, float* __restrict__ bcat) {
    int idx = blockIdx.x * blockDim.x + threadIdx.x;
    if (idx >= NL_ * 640) return;
    int L = idx / 640, c = idx % 640;
    float v;
    if (c < 256)      v = bv  [L * 256 + c];
    else if (c < 512) v = boff[L * 256 + c - 256];
    else              v = bat [L * 128 + c - 512];
    bcat[idx] = v;
}

// xp0 = split(src + pos)
__global__ void add0_split(const float* __restrict__ a, const float* __restrict__ b,
                           __nv_bfloat16* __restrict__ oh, __nv_bfloat16* __restrict__ ol,
                           int n2) {
    int i = blockIdx.x * blockDim.x + threadIdx.x;
    if (i >= n2) return;
    float2 av = reinterpret_cast<const float2*>(a)[i];
    float2 bv = reinterpret_cast<const float2*>(b)[i];
    float v0 = av.x + bv.x, v1 = av.y + bv.y;
    __nv_bfloat16 h0, l0, h1, l1;
    split2(v0, h0, l0); split2(v1, h1, l1);
    reinterpret_cast<__nv_bfloat162*>(oh)[i] = __nv_bfloat162(h0, h1);
    reinterpret_cast<__nv_bfloat162*>(ol)[i] = __nv_bfloat162(l0, l1);
}

// ---------------------------------------------------------------------------
// Split-bf16 HMMA GEMM: C[M,N] = (Ah+Al)[M,K] @ (Bh+Bl)[N,K]^T + bias
// 3 products: Ah*Bh + Ah*Bl + Al*Bh, fp32 accum. A and B both pre-split bf16,
// loaded via cp.async. Zero FFMA in mainloop.
// MODE 0: fp32 out. MODE 1: ReLU + split bf16 out (OH/OL).
// MODE 2: fused projection (N_=640): cols<256 -> fp16 VH; cols>=256 -> fp32 OA.
// Tile 128x128, BK=32, 256 threads (8 warps 2x4; warp tile 64x32), 2 stages.
// ---------------------------------------------------------------------------
#define OFF_AH 0
#define OFF_AL 10240
#define OFF_BH 20480
#define OFF_BL 30720
#define STAGE_BYTES 40960

template <int MODE>
__global__ __launch_bounds__(256, 2) void gemm_mma(
        const __nv_bfloat16* __restrict__ Ah, const __nv_bfloat16* __restrict__ Al,
        const __nv_bfloat16* __restrict__ Bh, const __nv_bfloat16* __restrict__ Bl,
        const float* __restrict__ bias,
        float* __restrict__ C, __half* __restrict__ VH, float* __restrict__ OA,
        __nv_bfloat16* __restrict__ OH, __nv_bfloat16* __restrict__ OL,
        int M, int K, int N_) {
    extern __shared__ char smem[];
    const uint32_t sbase = smem_u32(smem);
    const int tid  = threadIdx.x;
    const int wid  = tid >> 5;
    const int lane = tid & 31;
    const int warpM = wid >> 2;          // 0..1  -> M offset *64
    const int warpN = wid & 3;           // 0..3  -> N offset *32
    const int m0 = blockIdx.y * 128;
    const int n0 = blockIdx.x * 128;

    float acc[4][4][4];
    #pragma unroll
    for (int i = 0; i < 4; i++)
        #pragma unroll
        for (int j = 0; j < 4; j++)
            #pragma unroll
            for (int r = 0; r < 4; r++) acc[i][j][r] = 0.f;

    const int nkt = K >> 5;

    auto loadAB = [&](int kt, uint32_t stage_u) {
        #pragma unroll
        for (int i = 0; i < 2; i++) {
            int idx = tid + i * 256;              // 0..511
            int row = idx >> 2;                   // 0..127
            int ch  = (idx & 3) << 3;             // k offset 0,8,16,24
            size_t ga = (size_t)(m0 + row) * K + kt * 32 + ch;
            size_t gb = (size_t)(n0 + row) * K + kt * 32 + ch;
            uint32_t s = stage_u + row * 80 + ch * 2;
            cp_async16(s + OFF_AH, Ah + ga);
            cp_async16(s + OFF_AL, Al + ga);
            cp_async16(s + OFF_BH, Bh + gb);
            cp_async16(s + OFF_BL, Bl + gb);
        }
    };
    auto compute = [&](uint32_t stage_u) {
        const int ar = lane & 15;
        const int ak = (lane >> 4) << 3;
        const int bn = (lane & 7) + ((lane >> 4) << 3);   // 0..15
        const int bk = ((lane >> 3) & 1) << 3;
        #pragma unroll
        for (int kk = 0; kk < 32; kk += 16) {
            uint32_t bh[4][2], bl[4][2];
            #pragma unroll
            for (int j2 = 0; j2 < 2; j2++) {
                uint32_t r[4];
                uint32_t addr = stage_u + ((warpN * 32 + j2 * 16 + bn) * 40 + kk + bk) * 2;
                ldsm4(r, addr + OFF_BH);
                bh[j2*2][0]=r[0]; bh[j2*2][1]=r[1]; bh[j2*2+1][0]=r[2]; bh[j2*2+1][1]=r[3];
                ldsm4(r, addr + OFF_BL);
                bl[j2*2][0]=r[0]; bl[j2*2][1]=r[1]; bl[j2*2+1][0]=r[2]; bl[j2*2+1][1]=r[3];
            }
            #pragma unroll
            for (int i = 0; i < 4; i++) {
                uint32_t ah[4], al[4];
                uint32_t a = stage_u + ((warpM * 64 + i * 16 + ar) * 40 + kk + ak) * 2;
                ldsm4(ah, a + OFF_AH);
                ldsm4(al, a + OFF_AL);
                #pragma unroll
                for (int j = 0; j < 4; j++) {
                    mma16816(acc[i][j], ah, bh[j]);
                    mma16816(acc[i][j], ah, bl[j]);
                    mma16816(acc[i][j], al, bh[j]);
                }
            }
        }
    };

    // prologue
    loadAB(0, sbase);
    cp_commit();
    cp_wait0();
    __syncthreads();

    // main loop (double buffered)
    for (int kt = 0; kt < nkt; kt++) {
        const uint32_t cur = sbase + (uint32_t)(kt & 1) * STAGE_BYTES;
        const uint32_t nxt = sbase + (uint32_t)((kt + 1) & 1) * STAGE_BYTES;
        if (kt + 1 < nkt) {
            loadAB(kt + 1, nxt);
            cp_commit();
        }
        compute(cur);
        if (kt + 1 < nkt) cp_wait0();
        __syncthreads();
    }

    // epilogue
    const int tr = lane >> 2;
    const int tc = (lane & 3) * 2;
    #pragma unroll
    for (int i = 0; i < 4; i++) {
        #pragma unroll
        for (int j = 0; j < 4; j++) {
            int row = m0 + warpM * 64 + i * 16 + tr;
            int col = n0 + warpN * 32 + j * 8 + tc;
            float2 bb = *reinterpret_cast<const float2*>(bias + col);
            float2 o0, o1;
            o0.x = acc[i][j][0] + bb.x; o0.y = acc[i][j][1] + bb.y;
            o1.x = acc[i][j][2] + bb.x; o1.y = acc[i][j][3] + bb.y;
            if (MODE == 1) {
                o0.x = fmaxf(o0.x, 0.f); o0.y = fmaxf(o0.y, 0.f);
                o1.x = fmaxf(o1.x, 0.f); o1.y = fmaxf(o1.y, 0.f);
                __nv_bfloat16 h0, l0, h1, l1;
                split2(o0.x, h0, l0); split2(o0.y, h1, l1);
                *reinterpret_cast<__nv_bfloat162*>(OH + (size_t)row * N_ + col) = __nv_bfloat162(h0, h1);
                *reinterpret_cast<__nv_bfloat162*>(OL + (size_t)row * N_ + col) = __nv_bfloat162(l0, l1);
                split2(o1.x, h0, l0); split2(o1.y, h1, l1);
                *reinterpret_cast<__nv_bfloat162*>(OH + (size_t)(row + 8) * N_ + col) = __nv_bfloat162(h0, h1);
                *reinterpret_cast<__nv_bfloat162*>(OL + (size_t)(row + 8) * N_ + col) = __nv_bfloat162(l0, l1);
            } else if (MODE == 2) {
                if (n0 < 256) {
                    *reinterpret_cast<__half2*>(VH + (size_t)row * 256 + col) =
                        __floats2half2_rn(o0.x, o0.y);
                    *reinterpret_cast<__half2*>(VH + (size_t)(row + 8) * 256 + col) =
                        __floats2half2_rn(o1.x, o1.y);
                } else {
                    int co = col - 256;
                    *reinterpret_cast<float2*>(OA + (size_t)row * 384 + co) = o0;
                    *reinterpret_cast<float2*>(OA + (size_t)(row + 8) * 384 + co) = o1;
                }
            } else {
                *reinterpret_cast<float2*>(C + (size_t)row * N_ + col) = o0;
                *reinterpret_cast<float2*>(C + (size_t)(row + 8) * N_ + col) = o1;
            }
        }
    }
}

// ---------------------------------------------------------------------------
// Deformable sampling with inline softmax; v fp16, off/att fused (stride 384).
// One warp per (token, head); lane = channel. Output split bf16.
// ---------------------------------------------------------------------------
__global__ void deform_sample(const __half* __restrict__ vh,
                              const float* __restrict__ oa,
                              const float* __restrict__ ref,
                              __nv_bfloat16* __restrict__ outH,
                              __nv_bfloat16* __restrict__ outL) {
    int w = blockIdx.x * 8 + (threadIdx.x >> 5);
    if (w >= NTOK * NHEAD_) return;
    int lane = threadIdx.x & 31;
    int h = w & 7;
    int t = w >> 3;
    int b = t / LQ_;

    float rx = ref[t * 2 + 0];
    float ry = ref[t * 2 + 1];
    const float* op = oa + (size_t)t * 384 + h * 32;
    const float* lp = oa + (size_t)t * 384 + 256 + h * 16;

    float e[16];
    float m = -1e30f;
    #pragma unroll
    for (int j = 0; j < 16; j++) { e[j] = lp[j]; m = fmaxf(m, e[j]); }
    float s = 0.f;
    #pragma unroll
    for (int j = 0; j < 16; j++) { e[j] = expf(e[j] - m); s += e[j]; }
    float inv = 1.f / s;

    const int Ws[4]     = {128, 64, 32, 16};
    const int starts[4] = {0, 16384, 20480, 21504};

    float acc = 0.f;
    #pragma unroll
    for (int l = 0; l < 4; l++) {
        const int   W    = Ws[l];
        const float invW = 1.f / (float)W;
        const float Wm1  = (float)(W - 1);
        const __half* vb = vh + ((size_t)(b * LQ_ + starts[l])) * 256 + h * 32 + lane;
        #pragma unroll
        for (int k = 0; k < 4; k++) {
            float ox  = op[l * 8 + k * 2 + 0];
            float oy  = op[l * 8 + k * 2 + 1];
            float wgt = e[l * 4 + k] * inv;
            float x = (rx + ox * invW) * Wm1;
            float y = (ry + oy * invW) * Wm1;
            x = fminf(fmaxf(x, 0.f), Wm1);
            y = fminf(fmaxf(y, 0.f), Wm1);
            float x0f = floorf(x), y0f = floorf(y);
            float wx = x - x0f, wy = y - y0f;
            int x0 = (int)x0f, y0 = (int)y0f;
            int x1 = min(x0 + 1, W - 1);
            int y1 = min(y0 + 1, W - 1);
            const __half* r0 = vb + (size_t)(y0 * W) * 256;
            const __half* r1 = vb + (size_t)(y1 * W) * 256;
            float v00 = __half2float(r0[x0 * 256]);
            float v10 = __half2float(r0[x1 * 256]);
            float v01 = __half2float(r1[x0 * 256]);
            float v11 = __half2float(r1[x1 * 256]);
            float top = v00 + wx * (v10 - v00);
            float bot = v01 + wx * (v11 - v01);
            acc += wgt * (top + wy * (bot - top));
        }
    }
    __nv_bfloat16 hh, ll;
    split2(acc, hh, ll);
    outH[(size_t)t * 256 + h * 32 + lane] = hh;
    outL[(size_t)t * 256 + h * 32 + lane] = ll;
}

// ---------------------------------------------------------------------------
// LayerNorm( (aH+aL) + b ) over C=256, one warp per row.
// Writes split bf16 of (result [+ pos]) to outH/outL, or fp32 to out32.
// ---------------------------------------------------------------------------
__global__ void ln_kernel(const __nv_bfloat16* __restrict__ aH,
                          const __nv_bfloat16* __restrict__ aL,
                          const float* __restrict__ b,
                          const float* __restrict__ gm, const float* __restrict__ bt,
                          const float* __restrict__ pos,
                          __nv_bfloat16* __restrict__ outH, __nv_bfloat16* __restrict__ outL,
                          float* __restrict__ out32) {
    int row = blockIdx.x * 8 + (threadIdx.x >> 5);
    if (row >= NTOK) return;
    int lane = threadIdx.x & 31;
    const __nv_bfloat16* ah = aH + (size_t)row * 256;
    const __nv_bfloat16* al = aL + (size_t)row * 256;
    const float* bp = b + (size_t)row * 256;

    float vals[8];
    float s = 0.f;
    #pragma unroll
    for (int i = 0; i < 8; i++) {
        int c = lane + i * 32;
        vals[i] = __bfloat162float(ah[c]) + __bfloat162float(al[c]) + bp[c];
        s += vals[i];
    }
    #pragma unroll
    for (int o = 16; o; o >>= 1) s += __shfl_xor_sync(0xffffffffu, s, o);
    float mean = s * (1.f / 256.f);

    float var = 0.f;
    #pragma unroll
    for (int i = 0; i < 8; i++) { float d = vals[i] - mean; var += d * d; }
    #pragma unroll
    for (int o = 16; o; o >>= 1) var += __shfl_xor_sync(0xffffffffu, var, o);
    float rstd = rsqrtf(var * (1.f / 256.f) + 1e-5f);

    #pragma unroll
    for (int i = 0; i < 8; i++) {
        int c = lane + i * 32;
        float r = (vals[i] - mean) * rstd * gm[c] + bt[c];
        if (out32) {
            out32[(size_t)row * 256 + c] = r;
        } else {
            float w = pos ? (r + pos[(size_t)row * 256 + c]) : r;
            __nv_bfloat16 hh, ll;
            split2(w, hh, ll);
            outH[(size_t)row * 256 + c] = hh;
            outL[(size_t)row * 256 + c] = ll;
        }
    }
}

// ---------------------------------------------------------------------------
// Launch
// ---------------------------------------------------------------------------
extern "C" void kernel_launch(void* const* d_in, const int* in_sizes, int n_in,
                              void* d_out, int out_size) {
    const float* src  = (const float*)d_in[0];
    const float* pos  = (const float*)d_in[1];
    const float* ref  = (const float*)d_in[2];
    const float* Woff = (const float*)d_in[3];
    const float* boff = (const float*)d_in[4];
    const float* Wat  = (const float*)d_in[5];
    const float* bat  = (const float*)d_in[6];
    const float* Wv   = (const float*)d_in[7];
    const float* bv   = (const float*)d_in[8];
    const float* Wo   = (const float*)d_in[9];
    const float* bo   = (const float*)d_in[10];
    const float* W1   = (const float*)d_in[11];
    const float* b1   = (const float*)d_in[12];
    const float* W2   = (const float*)d_in[13];
    const float* b2   = (const float*)d_in[14];
    const float* n1s  = (const float*)d_in[15];
    const float* n1b  = (const float*)d_in[16];
    const float* n2s  = (const float*)d_in[17];
    const float* n2b  = (const float*)d_in[18];

    __nv_bfloat16 *xpH, *xpL, *xH, *xL, *aoH, *aoL, *hH, *hL;
    float *tmp, *oa, *bcat;
    __half* vh;
    __nv_bfloat16 *wch, *wcl, *woh, *wol, *w1h, *w1l, *w2h, *w2l;
    cudaGetSymbolAddress((void**)&xpH, g_xpH); cudaGetSymbolAddress((void**)&xpL, g_xpL);
    cudaGetSymbolAddress((void**)&xH,  g_xH);  cudaGetSymbolAddress((void**)&xL,  g_xL);
    cudaGetSymbolAddress((void**)&aoH, g_aoH); cudaGetSymbolAddress((void**)&aoL, g_aoL);
    cudaGetSymbolAddress((void**)&hH,  g_hH);  cudaGetSymbolAddress((void**)&hL,  g_hL);
    cudaGetSymbolAddress((void**)&tmp,  g_tmp);
    cudaGetSymbolAddress((void**)&vh,   g_vh);
    cudaGetSymbolAddress((void**)&oa,   g_oa);
    cudaGetSymbolAddress((void**)&bcat, g_bcat);
    cudaGetSymbolAddress((void**)&wch,  g_wcat_h);
    cudaGetSymbolAddress((void**)&wcl,  g_wcat_l);
    cudaGetSymbolAddress((void**)&woh,  g_wo_h);
    cudaGetSymbolAddress((void**)&wol,  g_wo_l);
    cudaGetSymbolAddress((void**)&w1h,  g_w1_h);
    cudaGetSymbolAddress((void**)&w1l,  g_w1_l);
    cudaGetSymbolAddress((void**)&w2h,  g_w2_h);
    cudaGetSymbolAddress((void**)&w2l,  g_w2_l);

    size_t shm = 2 * STAGE_BYTES;
    cudaFuncSetAttribute(gemm_mma<0>, cudaFuncAttributeMaxDynamicSharedMemorySize, (int)shm);
    cudaFuncSetAttribute(gemm_mma<1>, cudaFuncAttributeMaxDynamicSharedMemorySize, (int)shm);
    cudaFuncSetAttribute(gemm_mma<2>, cudaFuncAttributeMaxDynamicSharedMemorySize, (int)shm);

    // ---- one-time weight prep (all layers) ----
    prep_w<<<dim3(8, 8, NL_), dim3(32, 8)>>>(Wv,   wch,             wcl,             256, 256,
                                             (size_t)256 * 256, (size_t)640 * 256);
    prep_w<<<dim3(8, 8, NL_), dim3(32, 8)>>>(Woff, wch + 256 * 256, wcl + 256 * 256, 256, 256,
                                             (size_t)256 * 256, (size_t)640 * 256);
    prep_w<<<dim3(4, 8, NL_), dim3(32, 8)>>>(Wat,  wch + 512 * 256, wcl + 512 * 256, 256, 128,
                                             (size_t)256 * 128, (size_t)640 * 256);
    prep_w<<<dim3(8, 8, NL_),  dim3(32, 8)>>>(Wo, woh, wol, 256, 256,
                                              (size_t)256 * 256,  (size_t)256 * 256);
    prep_w<<<dim3(32, 8, NL_), dim3(32, 8)>>>(W1, w1h, w1l, 256, 1024,
                                              (size_t)256 * 1024, (size_t)1024 * 256);
    prep_w<<<dim3(8, 32, NL_), dim3(32, 8)>>>(W2, w2h, w2l, 1024, 256,
                                              (size_t)1024 * 256, (size_t)256 * 1024);
    bias_cat<<<(NL_ * 640 + 255) / 256, 256>>>(bv, boff, bat, bcat);

    const int n2 = NTOK * C_ / 2;
    add0_split<<<(n2 + 255) / 256, 256>>>(src, pos, xpH, xpL, n2);

    dim3 gcat(640 / 128, NTOK / 128);    // (5, 340)
    dim3 g256(256 / 128, NTOK / 128);    // (2, 340)
    dim3 g1024(1024 / 128, NTOK / 128);  // (8, 340)

    for (int i = 0; i < NL_; i++) {
        // fused projection: v (fp16) + off/att (fp32)
        gemm_mma<2><<<gcat, 256, shm>>>(xpH, xpL,
                                        wch + (size_t)i * 640 * 256, wcl + (size_t)i * 640 * 256,
                                        bcat + i * 640, nullptr, vh, oa, nullptr, nullptr,
                                        NTOK, 256, 640);
        // sampling (softmax inlined), split output
        deform_sample<<<NTOK, 256>>>(vh, oa, ref, aoH, aoL);
        // output projection + LN1
        gemm_mma<0><<<g256, 256, shm>>>(aoH, aoL,
                                        woh + (size_t)i * 256 * 256, wol + (size_t)i * 256 * 256,
                                        bo + i * 256, tmp, nullptr, nullptr, nullptr, nullptr,
                                        NTOK, 256, 256);
        ln_kernel<<<NTOK / 8, 256>>>(xpH, xpL, tmp, n1s + i * 256, n1b + i * 256,
                                     nullptr, xH, xL, nullptr);
        // FFN + LN2 (fused +pos -> next xp)
        gemm_mma<1><<<g1024, 256, shm>>>(xH, xL,
                                         w1h + (size_t)i * 1024 * 256, w1l + (size_t)i * 1024 * 256,
                                         b1 + i * 1024, nullptr, nullptr, nullptr, hH, hL,
                                         NTOK, 256, 1024);
        gemm_mma<0><<<g256, 256, shm>>>(hH, hL,
                                        w2h + (size_t)i * 256 * 1024, w2l + (size_t)i * 256 * 1024,
                                        b2 + i * 256, tmp, nullptr, nullptr, nullptr, nullptr,
                                        NTOK, 1024, 256);
        bool last = (i == NL_ - 1);
        ln_kernel<<<NTOK / 8, 256>>>(xH, xL, tmp, n2s + i * 256, n2b + i * 256,
                                     last ? nullptr : pos,
                                     last ? nullptr : xpH, last ? nullptr : xpL,
                                     last ? (float*)d_out : nullptr);
    }
}

// round 10
// speedup vs baseline: 1.3538x; 1.3538x over previous
#include <cuda_runtime.h>
#include <cuda_bf16.h>
#include <cuda_fp16.h>
#include <math.h>
#include <stdint.h>

// Problem constants
#define NTOK  43520        // B * LQ
#define LQ_   21760
#define C_    256
#define NHEAD_ 8
#define FF_   1024
#define NL_   6

// ---------------------------------------------------------------------------
// Scratch (static device allocations; no cudaMalloc anywhere)
// Activations stored as split bf16 hi/lo plane pairs (fp32-equivalent).
// ---------------------------------------------------------------------------
__device__ __align__(16) __nv_bfloat16 g_xpH[NTOK * C_], g_xpL[NTOK * C_];
__device__ __align__(16) __nv_bfloat16 g_xH [NTOK * C_], g_xL [NTOK * C_];
__device__ __align__(16) __nv_bfloat16 g_aoH[NTOK * C_], g_aoL[NTOK * C_];
__device__ __align__(16) __nv_bfloat16 g_hH [NTOK * FF_], g_hL [NTOK * FF_];
__device__ float  g_tmp[NTOK * C_];
__device__ __half g_vh [NTOK * C_];        // value proj, fp16 (gather source)
__device__ float  g_oa [NTOK * 384];       // off (256) + att logits (128), fused

// pre-split weights, all layers: [N,K] bf16 hi/lo. Wcat padded to N=768.
__device__ __align__(16) __nv_bfloat16 g_wcat_h[NL_ * 768 * 256];
__device__ __align__(16) __nv_bfloat16 g_wcat_l[NL_ * 768 * 256];
__device__ __align__(16) __nv_bfloat16 g_wo_h  [NL_ * 256 * 256];
__device__ __align__(16) __nv_bfloat16 g_wo_l  [NL_ * 256 * 256];
__device__ __align__(16) __nv_bfloat16 g_w1_h  [NL_ * 1024 * 256];
__device__ __align__(16) __nv_bfloat16 g_w1_l  [NL_ * 1024 * 256];
__device__ __align__(16) __nv_bfloat16 g_w2_h  [NL_ * 256 * 1024];
__device__ __align__(16) __nv_bfloat16 g_w2_l  [NL_ * 256 * 1024];
__device__ float g_bcat[NL_ * 768];

// ---------------------------------------------------------------------------
// PTX helpers (sm_103 base target)
// ---------------------------------------------------------------------------
__device__ __forceinline__ uint32_t smem_u32(const void* p) {
    return (uint32_t)__cvta_generic_to_shared(p);
}
__device__ __forceinline__ void cp_async16(uint32_t saddr, const void* gaddr) {
    asm volatile("cp.async.cg.shared.global [%0], [%1], 16;" :: "r"(saddr), "l"(gaddr));
}
__device__ __forceinline__ void cp_commit() {
    asm volatile("cp.async.commit_group;" ::: "memory");
}
__device__ __forceinline__ void cp_wait0() {
    asm volatile("cp.async.wait_group 0;" ::: "memory");
}
__device__ __forceinline__ void ldsm4(uint32_t* r, uint32_t a) {
    asm volatile("ldmatrix.sync.aligned.m8n8.x4.shared.b16 {%0,%1,%2,%3}, [%4];"
                 : "=r"(r[0]), "=r"(r[1]), "=r"(r[2]), "=r"(r[3]) : "r"(a));
}
__device__ __forceinline__ void mma16816(float* c, const uint32_t* a, const uint32_t* b) {
    asm volatile("mma.sync.aligned.m16n8k16.row.col.f32.bf16.bf16.f32 "
                 "{%0,%1,%2,%3}, {%4,%5,%6,%7}, {%8,%9}, {%0,%1,%2,%3};"
                 : "+f"(c[0]), "+f"(c[1]), "+f"(c[2]), "+f"(c[3])
                 : "r"(a[0]), "r"(a[1]), "r"(a[2]), "r"(a[3]), "r"(b[0]), "r"(b[1]));
}
__device__ __forceinline__ void split2(float v, __nv_bfloat16& h, __nv_bfloat16& l) {
    h = __float2bfloat16(v);
    l = __float2bfloat16(v - __bfloat162float(h));
}

// ---------------------------------------------------------------------------
// Weight prep: W fp32 [K,N] slice -> Bt_hi/Bt_lo bf16 [N,K] (transpose + split)
// ---------------------------------------------------------------------------
__global__ void prep_w(const float* __restrict__ W, __nv_bfloat16* __restrict__ Bh,
                       __nv_bfloat16* __restrict__ Bl, int K, int N,
                       size_t srcLayerStride, size_t dstLayerStride) {
    const int L = blockIdx.z;
    W  += (size_t)L * srcLayerStride;
    Bh += (size_t)L * dstLayerStride;
    Bl += (size_t)L * dstLayerStride;
    __shared__ float t[32][33];
    int k0 = blockIdx.y * 32, n0 = blockIdx.x * 32;
    for (int i = threadIdx.y; i < 32; i += 8)
        t[i][threadIdx.x] = W[(size_t)(k0 + i) * N + n0 + threadIdx.x];
    __syncthreads();
    for (int i = threadIdx.y; i < 32; i += 8) {
        float x = t[threadIdx.x][i];
        __nv_bfloat16 h, l;
        split2(x, h, l);
        size_t o = (size_t)(n0 + i) * K + k0 + threadIdx.x;
        Bh[o] = h;
        Bl[o] = l;
    }
}

// zero-fill a bf16 range (pad rows of Wcat)
__global__ void zero_bf16(__nv_bfloat16* __restrict__ p, size_t n) {
    size_t i = (size_t)blockIdx.x * blockDim.x + threadIdx.x;
    if (i < n) p[i] = __float2bfloat16(0.f);
}

__global__ void bias_cat(const float* __restrict__ bv, const float* __restrict__ boff,
                         const float* __restrict__ bat, float* __restrict__ bcat) {
    int idx = blockIdx.x * blockDim.x + threadIdx.x;
    if (idx >= NL_ * 768) return;
    int L = idx / 768, c = idx % 768;
    float v = 0.f;
    if (c < 256)      v = bv  [L * 256 + c];
    else if (c < 512) v = boff[L * 256 + c - 256];
    else if (c < 640) v = bat [L * 128 + c - 512];
    bcat[idx] = v;
}

// xp0 = split(src + pos)
__global__ void add0_split(const float* __restrict__ a, const float* __restrict__ b,
                           __nv_bfloat16* __restrict__ oh, __nv_bfloat16* __restrict__ ol,
                           int n2) {
    int i = blockIdx.x * blockDim.x + threadIdx.x;
    if (i >= n2) return;
    float2 av = reinterpret_cast<const float2*>(a)[i];
    float2 bv = reinterpret_cast<const float2*>(b)[i];
    float v0 = av.x + bv.x, v1 = av.y + bv.y;
    __nv_bfloat16 h0, l0, h1, l1;
    split2(v0, h0, l0); split2(v1, h1, l1);
    reinterpret_cast<__nv_bfloat162*>(oh)[i] = __nv_bfloat162(h0, h1);
    reinterpret_cast<__nv_bfloat162*>(ol)[i] = __nv_bfloat162(l0, l1);
}

// ---------------------------------------------------------------------------
// Split-bf16 HMMA GEMM: C[M,N] = (Ah+Al)[M,K] @ (Bh+Bl)[N,K]^T + bias
// 3 products: Ah*Bh + Ah*Bl + Al*Bh, fp32 accum. Zero FFMA in mainloop.
// CTA tile 128x256, BK=32, 256 threads (8 warps 2x4; warp tile 64x64), 2 stages.
// MODE 0: fp32 out. MODE 1: ReLU + split bf16 out (OH/OL).
// MODE 2: fused projection (logical N=768): col<256 -> fp16 VH (stride 256);
//         256<=col<640 -> fp32 OA (stride 384); col>=640 -> discard (pad).
// ---------------------------------------------------------------------------
#define OFF_AH 0
#define OFF_AL 10240
#define OFF_BH 20480
#define OFF_BL 40960
#define STAGE_BYTES 61440

template <int MODE>
__global__ __launch_bounds__(256) void gemm_mma(
        const __nv_bfloat16* __restrict__ Ah, const __nv_bfloat16* __restrict__ Al,
        const __nv_bfloat16* __restrict__ Bh, const __nv_bfloat16* __restrict__ Bl,
        const float* __restrict__ bias,
        float* __restrict__ C, __half* __restrict__ VH, float* __restrict__ OA,
        __nv_bfloat16* __restrict__ OH, __nv_bfloat16* __restrict__ OL,
        int M, int K, int N_) {
    extern __shared__ char smem[];
    const uint32_t sbase = smem_u32(smem);
    const int tid  = threadIdx.x;
    const int wid  = tid >> 5;
    const int lane = tid & 31;
    const int warpM = wid >> 2;          // 0..1 -> M offset *64
    const int warpN = wid & 3;           // 0..3 -> N offset *64
    const int m0 = blockIdx.y * 128;
    const int n0 = blockIdx.x * 256;

    float acc[4][8][4];
    #pragma unroll
    for (int i = 0; i < 4; i++)
        #pragma unroll
        for (int j = 0; j < 8; j++)
            #pragma unroll
            for (int r = 0; r < 4; r++) acc[i][j][r] = 0.f;

    const int nkt = K >> 5;

    auto loadAB = [&](int kt, uint32_t stage_u) {
        // B: 256 rows x 32 k, 2 planes
        #pragma unroll
        for (int i = 0; i < 4; i++) {
            int idx = tid + i * 256;              // 0..1023
            int row = idx >> 2;                   // 0..255
            int ch  = (idx & 3) << 3;             // 0,8,16,24
            size_t gb = (size_t)(n0 + row) * K + kt * 32 + ch;
            uint32_t s = stage_u + row * 80 + ch * 2;
            cp_async16(s + OFF_BH, Bh + gb);
            cp_async16(s + OFF_BL, Bl + gb);
        }
        // A: 128 rows x 32 k, 2 planes
        #pragma unroll
        for (int i = 0; i < 2; i++) {
            int idx = tid + i * 256;              // 0..511
            int row = idx >> 2;                   // 0..127
            int ch  = (idx & 3) << 3;
            size_t ga = (size_t)(m0 + row) * K + kt * 32 + ch;
            uint32_t s = stage_u + row * 80 + ch * 2;
            cp_async16(s + OFF_AH, Ah + ga);
            cp_async16(s + OFF_AL, Al + ga);
        }
    };
    auto compute = [&](uint32_t stage_u) {
        const int ar = lane & 15;
        const int ak = (lane >> 4) << 3;
        const int bn = (lane & 7) + ((lane >> 4) << 3);   // 0..15
        const int bk = ((lane >> 3) & 1) << 3;
        #pragma unroll
        for (int kk = 0; kk < 32; kk += 16) {
            uint32_t bh[8][2], bl[8][2];
            #pragma unroll
            for (int j2 = 0; j2 < 4; j2++) {
                uint32_t r[4];
                uint32_t addr = stage_u + OFF_BH +
                                (warpN * 64 + j2 * 16 + bn) * 80 + (kk + bk) * 2;
                ldsm4(r, addr);
                bh[j2*2][0]=r[0]; bh[j2*2][1]=r[1]; bh[j2*2+1][0]=r[2]; bh[j2*2+1][1]=r[3];
                ldsm4(r, addr + (OFF_BL - OFF_BH));
                bl[j2*2][0]=r[0]; bl[j2*2][1]=r[1]; bl[j2*2+1][0]=r[2]; bl[j2*2+1][1]=r[3];
            }
            #pragma unroll
            for (int i = 0; i < 4; i++) {
                uint32_t ah[4], al[4];
                uint32_t a = stage_u + OFF_AH +
                             (warpM * 64 + i * 16 + ar) * 80 + (kk + ak) * 2;
                ldsm4(ah, a);
                ldsm4(al, a + OFF_AL);
                #pragma unroll
                for (int j = 0; j < 8; j++) {
                    mma16816(acc[i][j], ah, bh[j]);
                    mma16816(acc[i][j], ah, bl[j]);
                    mma16816(acc[i][j], al, bh[j]);
                }
            }
        }
    };

    // prologue
    loadAB(0, sbase);
    cp_commit();
    cp_wait0();
    __syncthreads();

    // main loop (double buffered)
    for (int kt = 0; kt < nkt; kt++) {
        const uint32_t cur = sbase + (uint32_t)(kt & 1) * STAGE_BYTES;
        const uint32_t nxt = sbase + (uint32_t)((kt + 1) & 1) * STAGE_BYTES;
        if (kt + 1 < nkt) {
            loadAB(kt + 1, nxt);
            cp_commit();
        }
        compute(cur);
        if (kt + 1 < nkt) cp_wait0();
        __syncthreads();
    }

    // epilogue
    const int tr = lane >> 2;
    const int tc = (lane & 3) * 2;
    #pragma unroll
    for (int i = 0; i < 4; i++) {
        #pragma unroll
        for (int j = 0; j < 8; j++) {
            int row = m0 + warpM * 64 + i * 16 + tr;
            int col = n0 + warpN * 64 + j * 8 + tc;
            float2 bb = *reinterpret_cast<const float2*>(bias + col);
            float2 o0, o1;
            o0.x = acc[i][j][0] + bb.x; o0.y = acc[i][j][1] + bb.y;
            o1.x = acc[i][j][2] + bb.x; o1.y = acc[i][j][3] + bb.y;
            if (MODE == 1) {
                o0.x = fmaxf(o0.x, 0.f); o0.y = fmaxf(o0.y, 0.f);
                o1.x = fmaxf(o1.x, 0.f); o1.y = fmaxf(o1.y, 0.f);
                __nv_bfloat16 h0, l0, h1, l1;
                split2(o0.x, h0, l0); split2(o0.y, h1, l1);
                *reinterpret_cast<__nv_bfloat162*>(OH + (size_t)row * N_ + col) = __nv_bfloat162(h0, h1);
                *reinterpret_cast<__nv_bfloat162*>(OL + (size_t)row * N_ + col) = __nv_bfloat162(l0, l1);
                split2(o1.x, h0, l0); split2(o1.y, h1, l1);
                *reinterpret_cast<__nv_bfloat162*>(OH + (size_t)(row + 8) * N_ + col) = __nv_bfloat162(h0, h1);
                *reinterpret_cast<__nv_bfloat162*>(OL + (size_t)(row + 8) * N_ + col) = __nv_bfloat162(l0, l1);
            } else if (MODE == 2) {
                if (col < 256) {
                    *reinterpret_cast<__half2*>(VH + (size_t)row * 256 + col) =
                        __floats2half2_rn(o0.x, o0.y);
                    *reinterpret_cast<__half2*>(VH + (size_t)(row + 8) * 256 + col) =
                        __floats2half2_rn(o1.x, o1.y);
                } else if (col < 640) {
                    int co = col - 256;
                    *reinterpret_cast<float2*>(OA + (size_t)row * 384 + co) = o0;
                    *reinterpret_cast<float2*>(OA + (size_t)(row + 8) * 384 + co) = o1;
                }   // col >= 640: padded, discard
            } else {
                *reinterpret_cast<float2*>(C + (size_t)row * N_ + col) = o0;
                *reinterpret_cast<float2*>(C + (size_t)(row + 8) * N_ + col) = o1;
            }
        }
    }
}

// ---------------------------------------------------------------------------
// Deformable sampling with inline softmax; v fp16, off/att fused (stride 384).
// One warp per (token, head); lane = channel. Output split bf16.
// ---------------------------------------------------------------------------
__global__ void deform_sample(const __half* __restrict__ vh,
                              const float* __restrict__ oa,
                              const float* __restrict__ ref,
                              __nv_bfloat16* __restrict__ outH,
                              __nv_bfloat16* __restrict__ outL) {
    int w = blockIdx.x * 8 + (threadIdx.x >> 5);
    if (w >= NTOK * NHEAD_) return;
    int lane = threadIdx.x & 31;
    int h = w & 7;
    int t = w >> 3;
    int b = t / LQ_;

    float rx = ref[t * 2 + 0];
    float ry = ref[t * 2 + 1];
    const float* op = oa + (size_t)t * 384 + h * 32;
    const float* lp = oa + (size_t)t * 384 + 256 + h * 16;

    float e[16];
    float m = -1e30f;
    #pragma unroll
    for (int j = 0; j < 16; j++) { e[j] = lp[j]; m = fmaxf(m, e[j]); }
    float s = 0.f;
    #pragma unroll
    for (int j = 0; j < 16; j++) { e[j] = expf(e[j] - m); s += e[j]; }
    float inv = 1.f / s;

    const int Ws[4]     = {128, 64, 32, 16};
    const int starts[4] = {0, 16384, 20480, 21504};

    float acc = 0.f;
    #pragma unroll
    for (int l = 0; l < 4; l++) {
        const int   W    = Ws[l];
        const float invW = 1.f / (float)W;
        const float Wm1  = (float)(W - 1);
        const __half* vb = vh + ((size_t)(b * LQ_ + starts[l])) * 256 + h * 32 + lane;
        #pragma unroll
        for (int k = 0; k < 4; k++) {
            float ox  = op[l * 8 + k * 2 + 0];
            float oy  = op[l * 8 + k * 2 + 1];
            float wgt = e[l * 4 + k] * inv;
            float x = (rx + ox * invW) * Wm1;
            float y = (ry + oy * invW) * Wm1;
            x = fminf(fmaxf(x, 0.f), Wm1);
            y = fminf(fmaxf(y, 0.f), Wm1);
            float x0f = floorf(x), y0f = floorf(y);
            float wx = x - x0f, wy = y - y0f;
            int x0 = (int)x0f, y0 = (int)y0f;
            int x1 = min(x0 + 1, W - 1);
            int y1 = min(y0 + 1, W - 1);
            const __half* r0 = vb + (size_t)(y0 * W) * 256;
            const __half* r1 = vb + (size_t)(y1 * W) * 256;
            float v00 = __half2float(r0[x0 * 256]);
            float v10 = __half2float(r0[x1 * 256]);
            float v01 = __half2float(r1[x0 * 256]);
            float v11 = __half2float(r1[x1 * 256]);
            float top = v00 + wx * (v10 - v00);
            float bot = v01 + wx * (v11 - v01);
            acc += wgt * (top + wy * (bot - top));
        }
    }
    __nv_bfloat16 hh, ll;
    split2(acc, hh, ll);
    outH[(size_t)t * 256 + h * 32 + lane] = hh;
    outL[(size_t)t * 256 + h * 32 + lane] = ll;
}

// ---------------------------------------------------------------------------
// LayerNorm( (aH+aL) + b ) over C=256, one warp per row.
// Writes split bf16 of (result [+ pos]) to outH/outL, or fp32 to out32.
// ---------------------------------------------------------------------------
__global__ void ln_kernel(const __nv_bfloat16* __restrict__ aH,
                          const __nv_bfloat16* __restrict__ aL,
                          const float* __restrict__ b,
                          const float* __restrict__ gm, const float* __restrict__ bt,
                          const float* __restrict__ pos,
                          __nv_bfloat16* __restrict__ outH, __nv_bfloat16* __restrict__ outL,
                          float* __restrict__ out32) {
    int row = blockIdx.x * 8 + (threadIdx.x >> 5);
    if (row >= NTOK) return;
    int lane = threadIdx.x & 31;
    const __nv_bfloat16* ah = aH + (size_t)row * 256;
    const __nv_bfloat16* al = aL + (size_t)row * 256;
    const float* bp = b + (size_t)row * 256;

    float vals[8];
    float s = 0.f;
    #pragma unroll
    for (int i = 0; i < 8; i++) {
        int c = lane + i * 32;
        vals[i] = __bfloat162float(ah[c]) + __bfloat162float(al[c]) + bp[c];
        s += vals[i];
    }
    #pragma unroll
    for (int o = 16; o; o >>= 1) s += __shfl_xor_sync(0xffffffffu, s, o);
    float mean = s * (1.f / 256.f);

    float var = 0.f;
    #pragma unroll
    for (int i = 0; i < 8; i++) { float d = vals[i] - mean; var += d * d; }
    #pragma unroll
    for (int o = 16; o; o >>= 1) var += __shfl_xor_sync(0xffffffffu, var, o);
    float rstd = rsqrtf(var * (1.f / 256.f) + 1e-5f);

    #pragma unroll
    for (int i = 0; i < 8; i++) {
        int c = lane + i * 32;
        float r = (vals[i] - mean) * rstd * gm[c] + bt[c];
        if (out32) {
            out32[(size_t)row * 256 + c] = r;
        } else {
            float w = pos ? (r + pos[(size_t)row * 256 + c]) : r;
            __nv_bfloat16 hh, ll;
            split2(w, hh, ll);
            outH[(size_t)row * 256 + c] = hh;
            outL[(size_t)row * 256 + c] = ll;
        }
    }
}

// ---------------------------------------------------------------------------
// Launch
// ---------------------------------------------------------------------------
extern "C" void kernel_launch(void* const* d_in, const int* in_sizes, int n_in,
                              void* d_out, int out_size) {
    const float* src  = (const float*)d_in[0];
    const float* pos  = (const float*)d_in[1];
    const float* ref  = (const float*)d_in[2];
    const float* Woff = (const float*)d_in[3];
    const float* boff = (const float*)d_in[4];
    const float* Wat  = (const float*)d_in[5];
    const float* bat  = (const float*)d_in[6];
    const float* Wv   = (const float*)d_in[7];
    const float* bv   = (const float*)d_in[8];
    const float* Wo   = (const float*)d_in[9];
    const float* bo   = (const float*)d_in[10];
    const float* W1   = (const float*)d_in[11];
    const float* b1   = (const float*)d_in[12];
    const float* W2   = (const float*)d_in[13];
    const float* b2   = (const float*)d_in[14];
    const float* n1s  = (const float*)d_in[15];
    const float* n1b  = (const float*)d_in[16];
    const float* n2s  = (const float*)d_in[17];
    const float* n2b  = (const float*)d_in[18];

    __nv_bfloat16 *xpH, *xpL, *xH, *xL, *aoH, *aoL, *hH, *hL;
    float *tmp, *oa, *bcat;
    __half* vh;
    __nv_bfloat16 *wch, *wcl, *woh, *wol, *w1h, *w1l, *w2h, *w2l;
    cudaGetSymbolAddress((void**)&xpH, g_xpH); cudaGetSymbolAddress((void**)&xpL, g_xpL);
    cudaGetSymbolAddress((void**)&xH,  g_xH);  cudaGetSymbolAddress((void**)&xL,  g_xL);
    cudaGetSymbolAddress((void**)&aoH, g_aoH); cudaGetSymbolAddress((void**)&aoL, g_aoL);
    cudaGetSymbolAddress((void**)&hH,  g_hH);  cudaGetSymbolAddress((void**)&hL,  g_hL);
    cudaGetSymbolAddress((void**)&tmp,  g_tmp);
    cudaGetSymbolAddress((void**)&vh,   g_vh);
    cudaGetSymbolAddress((void**)&oa,   g_oa);
    cudaGetSymbolAddress((void**)&bcat, g_bcat);
    cudaGetSymbolAddress((void**)&wch,  g_wcat_h);
    cudaGetSymbolAddress((void**)&wcl,  g_wcat_l);
    cudaGetSymbolAddress((void**)&woh,  g_wo_h);
    cudaGetSymbolAddress((void**)&wol,  g_wo_l);
    cudaGetSymbolAddress((void**)&w1h,  g_w1_h);
    cudaGetSymbolAddress((void**)&w1l,  g_w1_l);
    cudaGetSymbolAddress((void**)&w2h,  g_w2_h);
    cudaGetSymbolAddress((void**)&w2l,  g_w2_l);

    size_t shm = 2 * STAGE_BYTES;   // 122880
    cudaFuncSetAttribute(gemm_mma<0>, cudaFuncAttributeMaxDynamicSharedMemorySize, (int)shm);
    cudaFuncSetAttribute(gemm_mma<1>, cudaFuncAttributeMaxDynamicSharedMemorySize, (int)shm);
    cudaFuncSetAttribute(gemm_mma<2>, cudaFuncAttributeMaxDynamicSharedMemorySize, (int)shm);

    // ---- one-time weight prep (all layers) ----
    // pad rows [640,768) of Wcat: zero so padded outputs are finite (discarded anyway)
    zero_bf16<<<(NL_ * 768 * 256 + 255) / 256, 256>>>(wch + 0, 0);  // no-op guard
    {
        size_t padStart = 640 * 256, padLen = 128 * 256;
        for (int L = 0; L < NL_; L++) {
            zero_bf16<<<((int)padLen + 255) / 256, 256>>>(wch + (size_t)L * 768 * 256 + padStart, padLen);
            zero_bf16<<<((int)padLen + 255) / 256, 256>>>(wcl + (size_t)L * 768 * 256 + padStart, padLen);
        }
    }
    prep_w<<<dim3(8, 8, NL_), dim3(32, 8)>>>(Wv,   wch,             wcl,             256, 256,
                                             (size_t)256 * 256, (size_t)768 * 256);
    prep_w<<<dim3(8, 8, NL_), dim3(32, 8)>>>(Woff, wch + 256 * 256, wcl + 256 * 256, 256, 256,
                                             (size_t)256 * 256, (size_t)768 * 256);
    prep_w<<<dim3(4, 8, NL_), dim3(32, 8)>>>(Wat,  wch + 512 * 256, wcl + 512 * 256, 256, 128,
                                             (size_t)256 * 128, (size_t)768 * 256);
    prep_w<<<dim3(8, 8, NL_),  dim3(32, 8)>>>(Wo, woh, wol, 256, 256,
                                              (size_t)256 * 256,  (size_t)256 * 256);
    prep_w<<<dim3(32, 8, NL_), dim3(32, 8)>>>(W1, w1h, w1l, 256, 1024,
                                              (size_t)256 * 1024, (size_t)1024 * 256);
    prep_w<<<dim3(8, 32, NL_), dim3(32, 8)>>>(W2, w2h, w2l, 1024, 256,
                                              (size_t)1024 * 256, (size_t)256 * 1024);
    bias_cat<<<(NL_ * 768 + 255) / 256, 256>>>(bv, boff, bat, bcat);

    const int n2 = NTOK * C_ / 2;
    add0_split<<<(n2 + 255) / 256, 256>>>(src, pos, xpH, xpL, n2);

    dim3 gcat(768 / 256, NTOK / 128);    // (3, 340)
    dim3 g256(256 / 256, NTOK / 128);    // (1, 340)
    dim3 g1024(1024 / 256, NTOK / 128);  // (4, 340)

    for (int i = 0; i < NL_; i++) {
        // fused projection: v (fp16) + off/att (fp32); N padded to 768
        gemm_mma<2><<<gcat, 256, shm>>>(xpH, xpL,
                                        wch + (size_t)i * 768 * 256, wcl + (size_t)i * 768 * 256,
                                        bcat + i * 768, nullptr, vh, oa, nullptr, nullptr,
                                        NTOK, 256, 768);
        // sampling (softmax inlined), split output
        deform_sample<<<NTOK, 256>>>(vh, oa, ref, aoH, aoL);
        // output projection + LN1
        gemm_mma<0><<<g256, 256, shm>>>(aoH, aoL,
                                        woh + (size_t)i * 256 * 256, wol + (size_t)i * 256 * 256,
                                        bo + i * 256, tmp, nullptr, nullptr, nullptr, nullptr,
                                        NTOK, 256, 256);
        ln_kernel<<<NTOK / 8, 256>>>(xpH, xpL, tmp, n1s + i * 256, n1b + i * 256,
                                     nullptr, xH, xL, nullptr);
        // FFN + LN2 (fused +pos -> next xp)
        gemm_mma<1><<<g1024, 256, shm>>>(xH, xL,
                                         w1h + (size_t)i * 1024 * 256, w1l + (size_t)i * 1024 * 256,
                                         b1 + i * 1024, nullptr, nullptr, nullptr, hH, hL,
                                         NTOK, 256, 1024);
        gemm_mma<0><<<g256, 256, shm>>>(hH, hL,
                                        w2h + (size_t)i * 256 * 1024, w2l + (size_t)i * 256 * 1024,
                                        b2 + i * 256, tmp, nullptr, nullptr, nullptr, nullptr,
                                        NTOK, 1024, 256);
        bool last = (i == NL_ - 1);
        ln_kernel<<<NTOK / 8, 256>>>(xH, xL, tmp, n2s + i * 256, n2b + i * 256,
                                     last ? nullptr : pos,
                                     last ? nullptr : xpH, last ? nullptr : xpL,
                                     last ? (float*)d_out : nullptr);
    }
}

// round 12
// speedup vs baseline: 1.3878x; 1.0251x over previous
#include <cuda_runtime.h>
#include <cuda_bf16.h>
#include <cuda_fp16.h>
#include <math.h>
#include <stdint.h>

// Problem constants
#define NTOK  43520        // B * LQ
#define LQ_   21760
#define C_    256
#define NHEAD_ 8
#define FF_   1024
#define NL_   6

// ---------------------------------------------------------------------------
// Scratch (static device allocations; no cudaMalloc anywhere)
// Activations stored as split bf16 hi/lo plane pairs (fp32-equivalent).
// ---------------------------------------------------------------------------
__device__ __align__(16) __nv_bfloat16 g_xpH[NTOK * C_], g_xpL[NTOK * C_];
__device__ __align__(16) __nv_bfloat16 g_xH [NTOK * C_], g_xL [NTOK * C_];
__device__ __align__(16) __nv_bfloat16 g_aoH[NTOK * C_], g_aoL[NTOK * C_];
__device__ __align__(16) __nv_bfloat16 g_hH [NTOK * FF_], g_hL [NTOK * FF_];
__device__ float  g_tmp[NTOK * C_];
__device__ __half g_vh [NTOK * C_];        // value proj, fp16 (gather source)
__device__ float  g_oa [NTOK * 384];       // off (256) + att logits (128), fused

// pre-split weights, all layers: [N,K] bf16 hi/lo
__device__ __align__(16) __nv_bfloat16 g_wcat_h[NL_ * 640 * 256];
__device__ __align__(16) __nv_bfloat16 g_wcat_l[NL_ * 640 * 256];
__device__ __align__(16) __nv_bfloat16 g_wo_h  [NL_ * 256 * 256];
__device__ __align__(16) __nv_bfloat16 g_wo_l  [NL_ * 256 * 256];
__device__ __align__(16) __nv_bfloat16 g_w1_h  [NL_ * 1024 * 256];
__device__ __align__(16) __nv_bfloat16 g_w1_l  [NL_ * 1024 * 256];
__device__ __align__(16) __nv_bfloat16 g_w2_h  [NL_ * 256 * 1024];
__device__ __align__(16) __nv_bfloat16 g_w2_l  [NL_ * 256 * 1024];
__device__ float g_bcat[NL_ * 640];

// ---------------------------------------------------------------------------
// PTX helpers (sm_103 base target)
// ---------------------------------------------------------------------------
__device__ __forceinline__ uint32_t smem_u32(const void* p) {
    return (uint32_t)__cvta_generic_to_shared(p);
}
__device__ __forceinline__ void cp_async16(uint32_t saddr, const void* gaddr) {
    asm volatile("cp.async.cg.shared.global [%0], [%1], 16;" :: "r"(saddr), "l"(gaddr));
}
__device__ __forceinline__ void cp_commit() {
    asm volatile("cp.async.commit_group;" ::: "memory");
}
__device__ __forceinline__ void cp_wait0() {
    asm volatile("cp.async.wait_group 0;" ::: "memory");
}
__device__ __forceinline__ void ldsm4(uint32_t* r, uint32_t a) {
    asm volatile("ldmatrix.sync.aligned.m8n8.x4.shared.b16 {%0,%1,%2,%3}, [%4];"
                 : "=r"(r[0]), "=r"(r[1]), "=r"(r[2]), "=r"(r[3]) : "r"(a));
}
__device__ __forceinline__ void mma16816(float* c, const uint32_t* a, const uint32_t* b) {
    asm volatile("mma.sync.aligned.m16n8k16.row.col.f32.bf16.bf16.f32 "
                 "{%0,%1,%2,%3}, {%4,%5,%6,%7}, {%8,%9}, {%0,%1,%2,%3};"
                 : "+f"(c[0]), "+f"(c[1]), "+f"(c[2]), "+f"(c[3])
                 : "r"(a[0]), "r"(a[1]), "r"(a[2]), "r"(a[3]), "r"(b[0]), "r"(b[1]));
}
__device__ __forceinline__ void split2(float v, __nv_bfloat16& h, __nv_bfloat16& l) {
    h = __float2bfloat16(v);
    l = __float2bfloat16(v - __bfloat162float(h));
}

// ---------------------------------------------------------------------------
// Weight prep: W fp32 [K,N] slice -> Bt_hi/Bt_lo bf16 [N,K] (transpose + split)
// ---------------------------------------------------------------------------
__global__ void prep_w(const float* __restrict__ W, __nv_bfloat16* __restrict__ Bh,
                       __nv_bfloat16* __restrict__ Bl, int K, int N,
                       size_t srcLayerStride, size_t dstLayerStride) {
    const int L = blockIdx.z;
    W  += (size_t)L * srcLayerStride;
    Bh += (size_t)L * dstLayerStride;
    Bl += (size_t)L * dstLayerStride;
    __shared__ float t[32][33];
    int k0 = blockIdx.y * 32, n0 = blockIdx.x * 32;
    for (int i = threadIdx.y; i < 32; i += 8)
        t[i][threadIdx.x] = W[(size_t)(k0 + i) * N + n0 + threadIdx.x];
    __syncthreads();
    for (int i = threadIdx.y; i < 32; i += 8) {
        float x = t[threadIdx.x][i];
        __nv_bfloat16 h, l;
        split2(x, h, l);
        size_t o = (size_t)(n0 + i) * K + k0 + threadIdx.x;
        Bh[o] = h;
        Bl[o] = l;
    }
}

// Concatenated projection-weight prep: [Wv | Woff | Wat] -> [640,256] per layer
__global__ void prep_cat(const float* __restrict__ Wv, const float* __restrict__ Woff,
                         const float* __restrict__ Wat,
                         __nv_bfloat16* __restrict__ Bh, __nv_bfloat16* __restrict__ Bl) {
    const int L = blockIdx.z;
    const int n0 = blockIdx.x * 32;     // 0..639 in 32-col tiles
    const int k0 = blockIdx.y * 32;
    const float* W;
    int srcN, ncol;
    if (n0 < 256)      { W = Wv   + (size_t)L * 256 * 256; srcN = 256; ncol = n0; }
    else if (n0 < 512) { W = Woff + (size_t)L * 256 * 256; srcN = 256; ncol = n0 - 256; }
    else               { W = Wat  + (size_t)L * 256 * 128; srcN = 128; ncol = n0 - 512; }
    Bh += (size_t)L * 640 * 256;
    Bl += (size_t)L * 640 * 256;
    __shared__ float t[32][33];
    for (int i = threadIdx.y; i < 32; i += 8)
        t[i][threadIdx.x] = W[(size_t)(k0 + i) * srcN + ncol + threadIdx.x];
    __syncthreads();
    for (int i = threadIdx.y; i < 32; i += 8) {
        float x = t[threadIdx.x][i];
        __nv_bfloat16 h, l;
        split2(x, h, l);
        size_t o = (size_t)(n0 + i) * 256 + k0 + threadIdx.x;
        Bh[o] = h;
        Bl[o] = l;
    }
}

// fused: xp0 = split(src + pos) AND bias concat (idx < NL*640)
__global__ void add0_bias(const float* __restrict__ a, const float* __restrict__ b,
                          __nv_bfloat16* __restrict__ oh, __nv_bfloat16* __restrict__ ol,
                          int n2,
                          const float* __restrict__ bv, const float* __restrict__ boff,
                          const float* __restrict__ bat, float* __restrict__ bcat) {
    int i = blockIdx.x * blockDim.x + threadIdx.x;
    if (i < NL_ * 640) {
        int L = i / 640, c = i % 640;
        float v;
        if (c < 256)      v = bv  [L * 256 + c];
        else if (c < 512) v = boff[L * 256 + c - 256];
        else              v = bat [L * 128 + c - 512];
        bcat[i] = v;
    }
    if (i >= n2) return;
    float2 av = reinterpret_cast<const float2*>(a)[i];
    float2 bv2 = reinterpret_cast<const float2*>(b)[i];
    float v0 = av.x + bv2.x, v1 = av.y + bv2.y;
    __nv_bfloat16 h0, l0, h1, l1;
    split2(v0, h0, l0); split2(v1, h1, l1);
    reinterpret_cast<__nv_bfloat162*>(oh)[i] = __nv_bfloat162(h0, h1);
    reinterpret_cast<__nv_bfloat162*>(ol)[i] = __nv_bfloat162(l0, l1);
}

// ---------------------------------------------------------------------------
// Split-bf16 HMMA GEMM: C[M,N] = (Ah+Al)[M,K] @ (Bh+Bl)[N,K]^T + bias
// 3 products: Ah*Bh + Ah*Bl + Al*Bh, fp32 accum. Zero FFMA in mainloop.
// CTA tile 128x128, BK=32, **512 threads = 16 warps (4x4; warp tile 32x32)**
// -> 4 warps/SMSP for latency hiding. 2-stage double buffer.
// MODE 0: fp32 out. MODE 1: ReLU + split bf16 out (OH/OL).
// MODE 2: fused projection (N=640): col<256 -> fp16 VH; col>=256 -> fp32 OA.
// ---------------------------------------------------------------------------
#define OFF_AH 0
#define OFF_AL 10240
#define OFF_BH 20480
#define OFF_BL 30720
#define STAGE_BYTES 40960

template <int MODE>
__global__ __launch_bounds__(512) void gemm_mma(
        const __nv_bfloat16* __restrict__ Ah, const __nv_bfloat16* __restrict__ Al,
        const __nv_bfloat16* __restrict__ Bh, const __nv_bfloat16* __restrict__ Bl,
        const float* __restrict__ bias,
        float* __restrict__ C, __half* __restrict__ VH, float* __restrict__ OA,
        __nv_bfloat16* __restrict__ OH, __nv_bfloat16* __restrict__ OL,
        int M, int K, int N_) {
    extern __shared__ char smem[];
    const uint32_t sbase = smem_u32(smem);
    const int tid  = threadIdx.x;
    const int wid  = tid >> 5;
    const int lane = tid & 31;
    const int warpM = wid >> 2;          // 0..3 -> M offset *32
    const int warpN = wid & 3;           // 0..3 -> N offset *32
    const int m0 = blockIdx.y * 128;
    const int n0 = blockIdx.x * 128;

    float acc[2][4][4];
    #pragma unroll
    for (int i = 0; i < 2; i++)
        #pragma unroll
        for (int j = 0; j < 4; j++)
            #pragma unroll
            for (int r = 0; r < 4; r++) acc[i][j][r] = 0.f;

    const int nkt = K >> 5;

    auto loadAB = [&](int kt, uint32_t stage_u) {
        int row = tid >> 2;                   // 0..127
        int ch  = (tid & 3) << 3;             // 0,8,16,24
        size_t ga = (size_t)(m0 + row) * K + kt * 32 + ch;
        size_t gb = (size_t)(n0 + row) * K + kt * 32 + ch;
        uint32_t s = stage_u + row * 80 + ch * 2;
        cp_async16(s + OFF_AH, Ah + ga);
        cp_async16(s + OFF_AL, Al + ga);
        cp_async16(s + OFF_BH, Bh + gb);
        cp_async16(s + OFF_BL, Bl + gb);
    };
    auto compute = [&](uint32_t stage_u) {
        const int ar = lane & 15;
        const int ak = (lane >> 4) << 3;
        const int bn = (lane & 7) + ((lane >> 4) << 3);   // 0..15
        const int bk = ((lane >> 3) & 1) << 3;
        #pragma unroll
        for (int kk = 0; kk < 32; kk += 16) {
            uint32_t bh[4][2], bl[4][2];
            #pragma unroll
            for (int j2 = 0; j2 < 2; j2++) {
                uint32_t r[4];
                uint32_t addr = stage_u + OFF_BH +
                                (warpN * 32 + j2 * 16 + bn) * 80 + (kk + bk) * 2;
                ldsm4(r, addr);
                bh[j2*2][0]=r[0]; bh[j2*2][1]=r[1]; bh[j2*2+1][0]=r[2]; bh[j2*2+1][1]=r[3];
                ldsm4(r, addr + (OFF_BL - OFF_BH));
                bl[j2*2][0]=r[0]; bl[j2*2][1]=r[1]; bl[j2*2+1][0]=r[2]; bl[j2*2+1][1]=r[3];
            }
            #pragma unroll
            for (int i = 0; i < 2; i++) {
                uint32_t ah[4], al[4];
                uint32_t a = stage_u + OFF_AH +
                             (warpM * 32 + i * 16 + ar) * 80 + (kk + ak) * 2;
                ldsm4(ah, a);
                ldsm4(al, a + OFF_AL);
                #pragma unroll
                for (int j = 0; j < 4; j++) {
                    mma16816(acc[i][j], ah, bh[j]);
                    mma16816(acc[i][j], ah, bl[j]);
                    mma16816(acc[i][j], al, bh[j]);
                }
            }
        }
    };

    // prologue
    loadAB(0, sbase);
    cp_commit();
    cp_wait0();
    __syncthreads();

    // main loop (double buffered)
    for (int kt = 0; kt < nkt; kt++) {
        const uint32_t cur = sbase + (uint32_t)(kt & 1) * STAGE_BYTES;
        const uint32_t nxt = sbase + (uint32_t)((kt + 1) & 1) * STAGE_BYTES;
        if (kt + 1 < nkt) {
            loadAB(kt + 1, nxt);
            cp_commit();
        }
        compute(cur);
        if (kt + 1 < nkt) cp_wait0();
        __syncthreads();
    }

    // epilogue
    const int tr = lane >> 2;
    const int tc = (lane & 3) * 2;
    #pragma unroll
    for (int i = 0; i < 2; i++) {
        #pragma unroll
        for (int j = 0; j < 4; j++) {
            int row = m0 + warpM * 32 + i * 16 + tr;
            int col = n0 + warpN * 32 + j * 8 + tc;
            float2 bb = *reinterpret_cast<const float2*>(bias + col);
            float2 o0, o1;
            o0.x = acc[i][j][0] + bb.x; o0.y = acc[i][j][1] + bb.y;
            o1.x = acc[i][j][2] + bb.x; o1.y = acc[i][j][3] + bb.y;
            if (MODE == 1) {
                o0.x = fmaxf(o0.x, 0.f); o0.y = fmaxf(o0.y, 0.f);
                o1.x = fmaxf(o1.x, 0.f); o1.y = fmaxf(o1.y, 0.f);
                __nv_bfloat16 h0, l0, h1, l1;
                split2(o0.x, h0, l0); split2(o0.y, h1, l1);
                *reinterpret_cast<__nv_bfloat162*>(OH + (size_t)row * N_ + col) = __nv_bfloat162(h0, h1);
                *reinterpret_cast<__nv_bfloat162*>(OL + (size_t)row * N_ + col) = __nv_bfloat162(l0, l1);
                split2(o1.x, h0, l0); split2(o1.y, h1, l1);
                *reinterpret_cast<__nv_bfloat162*>(OH + (size_t)(row + 8) * N_ + col) = __nv_bfloat162(h0, h1);
                *reinterpret_cast<__nv_bfloat162*>(OL + (size_t)(row + 8) * N_ + col) = __nv_bfloat162(l0, l1);
            } else if (MODE == 2) {
                if (col < 256) {
                    *reinterpret_cast<__half2*>(VH + (size_t)row * 256 + col) =
                        __floats2half2_rn(o0.x, o0.y);
                    *reinterpret_cast<__half2*>(VH + (size_t)(row + 8) * 256 + col) =
                        __floats2half2_rn(o1.x, o1.y);
                } else {
                    int co = col - 256;
                    *reinterpret_cast<float2*>(OA + (size_t)row * 384 + co) = o0;
                    *reinterpret_cast<float2*>(OA + (size_t)(row + 8) * 384 + co) = o1;
                }
            } else {
                *reinterpret_cast<float2*>(C + (size_t)row * N_ + col) = o0;
                *reinterpret_cast<float2*>(C + (size_t)(row + 8) * N_ + col) = o1;
            }
        }
    }
}

// ---------------------------------------------------------------------------
// Deformable sampling with inline softmax; v fp16, off/att fused (stride 384).
// One warp per (token, head); lane = channel. Output split bf16.
// ---------------------------------------------------------------------------
__global__ void deform_sample(const __half* __restrict__ vh,
                              const float* __restrict__ oa,
                              const float* __restrict__ ref,
                              __nv_bfloat16* __restrict__ outH,
                              __nv_bfloat16* __restrict__ outL) {
    int w = blockIdx.x * 8 + (threadIdx.x >> 5);
    if (w >= NTOK * NHEAD_) return;
    int lane = threadIdx.x & 31;
    int h = w & 7;
    int t = w >> 3;
    int b = t / LQ_;

    float rx = ref[t * 2 + 0];
    float ry = ref[t * 2 + 1];
    const float* op = oa + (size_t)t * 384 + h * 32;
    const float* lp = oa + (size_t)t * 384 + 256 + h * 16;

    float e[16];
    float m = -1e30f;
    #pragma unroll
    for (int j = 0; j < 16; j++) { e[j] = lp[j]; m = fmaxf(m, e[j]); }
    float s = 0.f;
    #pragma unroll
    for (int j = 0; j < 16; j++) { e[j] = expf(e[j] - m); s += e[j]; }
    float inv = 1.f / s;

    const int Ws[4]     = {128, 64, 32, 16};
    const int starts[4] = {0, 16384, 20480, 21504};

    float acc = 0.f;
    #pragma unroll
    for (int l = 0; l < 4; l++) {
        const int   W    = Ws[l];
        const float invW = 1.f / (float)W;
        const float Wm1  = (float)(W - 1);
        const __half* vb = vh + ((size_t)(b * LQ_ + starts[l])) * 256 + h * 32 + lane;
        #pragma unroll
        for (int k = 0; k < 4; k++) {
            float ox  = op[l * 8 + k * 2 + 0];
            float oy  = op[l * 8 + k * 2 + 1];
            float wgt = e[l * 4 + k] * inv;
            float x = (rx + ox * invW) * Wm1;
            float y = (ry + oy * invW) * Wm1;
            x = fminf(fmaxf(x, 0.f), Wm1);
            y = fminf(fmaxf(y, 0.f), Wm1);
            float x0f = floorf(x), y0f = floorf(y);
            float wx = x - x0f, wy = y - y0f;
            int x0 = (int)x0f, y0 = (int)y0f;
            int x1 = min(x0 + 1, W - 1);
            int y1 = min(y0 + 1, W - 1);
            const __half* r0 = vb + (size_t)(y0 * W) * 256;
            const __half* r1 = vb + (size_t)(y1 * W) * 256;
            float v00 = __half2float(r0[x0 * 256]);
            float v10 = __half2float(r0[x1 * 256]);
            float v01 = __half2float(r1[x0 * 256]);
            float v11 = __half2float(r1[x1 * 256]);
            float top = v00 + wx * (v10 - v00);
            float bot = v01 + wx * (v11 - v01);
            acc += wgt * (top + wy * (bot - top));
        }
    }
    __nv_bfloat16 hh, ll;
    split2(acc, hh, ll);
    outH[(size_t)t * 256 + h * 32 + lane] = hh;
    outL[(size_t)t * 256 + h * 32 + lane] = ll;
}

// ---------------------------------------------------------------------------
// LayerNorm( (aH+aL) + b ) over C=256, one warp per row.
// Writes split bf16 of (result [+ pos]) to outH/outL, or fp32 to out32.
// ---------------------------------------------------------------------------
__global__ void ln_kernel(const __nv_bfloat16* __restrict__ aH,
                          const __nv_bfloat16* __restrict__ aL,
                          const float* __restrict__ b,
                          const float* __restrict__ gm, const float* __restrict__ bt,
                          const float* __restrict__ pos,
                          __nv_bfloat16* __restrict__ outH, __nv_bfloat16* __restrict__ outL,
                          float* __restrict__ out32) {
    int row = blockIdx.x * 8 + (threadIdx.x >> 5);
    if (row >= NTOK) return;
    int lane = threadIdx.x & 31;
    const __nv_bfloat16* ah = aH + (size_t)row * 256;
    const __nv_bfloat16* al = aL + (size_t)row * 256;
    const float* bp = b + (size_t)row * 256;

    float vals[8];
    float s = 0.f;
    #pragma unroll
    for (int i = 0; i < 8; i++) {
        int c = lane + i * 32;
        vals[i] = __bfloat162float(ah[c]) + __bfloat162float(al[c]) + bp[c];
        s += vals[i];
    }
    #pragma unroll
    for (int o = 16; o; o >>= 1) s += __shfl_xor_sync(0xffffffffu, s, o);
    float mean = s * (1.f / 256.f);

    float var = 0.f;
    #pragma unroll
    for (int i = 0; i < 8; i++) { float d = vals[i] - mean; var += d * d; }
    #pragma unroll
    for (int o = 16; o; o >>= 1) var += __shfl_xor_sync(0xffffffffu, var, o);
    float rstd = rsqrtf(var * (1.f / 256.f) + 1e-5f);

    #pragma unroll
    for (int i = 0; i < 8; i++) {
        int c = lane + i * 32;
        float r = (vals[i] - mean) * rstd * gm[c] + bt[c];
        if (out32) {
            out32[(size_t)row * 256 + c] = r;
        } else {
            float w = pos ? (r + pos[(size_t)row * 256 + c]) : r;
            __nv_bfloat16 hh, ll;
            split2(w, hh, ll);
            outH[(size_t)row * 256 + c] = hh;
            outL[(size_t)row * 256 + c] = ll;
        }
    }
}

// ---------------------------------------------------------------------------
// Launch.  Launch order puts the fused projection GEMM at launch #6 so the
// ncu capture (-s 5 -c 1) profiles it next round.
// ---------------------------------------------------------------------------
extern "C" void kernel_launch(void* const* d_in, const int* in_sizes, int n_in,
                              void* d_out, int out_size) {
    const float* src  = (const float*)d_in[0];
    const float* pos  = (const float*)d_in[1];
    const float* ref  = (const float*)d_in[2];
    const float* Woff = (const float*)d_in[3];
    const float* boff = (const float*)d_in[4];
    const float* Wat  = (const float*)d_in[5];
    const float* bat  = (const float*)d_in[6];
    const float* Wv   = (const float*)d_in[7];
    const float* bv   = (const float*)d_in[8];
    const float* Wo   = (const float*)d_in[9];
    const float* bo   = (const float*)d_in[10];
    const float* W1   = (const float*)d_in[11];
    const float* b1   = (const float*)d_in[12];
    const float* W2   = (const float*)d_in[13];
    const float* b2   = (const float*)d_in[14];
    const float* n1s  = (const float*)d_in[15];
    const float* n1b  = (const float*)d_in[16];
    const float* n2s  = (const float*)d_in[17];
    const float* n2b  = (const float*)d_in[18];

    __nv_bfloat16 *xpH, *xpL, *xH, *xL, *aoH, *aoL, *hH, *hL;
    float *tmp, *oa, *bcat;
    __half* vh;
    __nv_bfloat16 *wch, *wcl, *woh, *wol, *w1h, *w1l, *w2h, *w2l;
    cudaGetSymbolAddress((void**)&xpH, g_xpH); cudaGetSymbolAddress((void**)&xpL, g_xpL);
    cudaGetSymbolAddress((void**)&xH,  g_xH);  cudaGetSymbolAddress((void**)&xL,  g_xL);
    cudaGetSymbolAddress((void**)&aoH, g_aoH); cudaGetSymbolAddress((void**)&aoL, g_aoL);
    cudaGetSymbolAddress((void**)&hH,  g_hH);  cudaGetSymbolAddress((void**)&hL,  g_hL);
    cudaGetSymbolAddress((void**)&tmp,  g_tmp);
    cudaGetSymbolAddress((void**)&vh,   g_vh);
    cudaGetSymbolAddress((void**)&oa,   g_oa);
    cudaGetSymbolAddress((void**)&bcat, g_bcat);
    cudaGetSymbolAddress((void**)&wch,  g_wcat_h);
    cudaGetSymbolAddress((void**)&wcl,  g_wcat_l);
    cudaGetSymbolAddress((void**)&woh,  g_wo_h);
    cudaGetSymbolAddress((void**)&wol,  g_wo_l);
    cudaGetSymbolAddress((void**)&w1h,  g_w1_h);
    cudaGetSymbolAddress((void**)&w1l,  g_w1_l);
    cudaGetSymbolAddress((void**)&w2h,  g_w2_h);
    cudaGetSymbolAddress((void**)&w2l,  g_w2_l);

    size_t shm = 2 * STAGE_BYTES;   // 81920
    cudaFuncSetAttribute(gemm_mma<0>, cudaFuncAttributeMaxDynamicSharedMemorySize, (int)shm);
    cudaFuncSetAttribute(gemm_mma<1>, cudaFuncAttributeMaxDynamicSharedMemorySize, (int)shm);
    cudaFuncSetAttribute(gemm_mma<2>, cudaFuncAttributeMaxDynamicSharedMemorySize, (int)shm);

    // ---- exactly 5 launches before the first GEMM ----
    prep_cat<<<dim3(20, 8, NL_), dim3(32, 8)>>>(Wv, Woff, Wat, wch, wcl);            // 1
    prep_w<<<dim3(8, 8, NL_),  dim3(32, 8)>>>(Wo, woh, wol, 256, 256,
                                              (size_t)256 * 256,  (size_t)256 * 256); // 2
    prep_w<<<dim3(32, 8, NL_), dim3(32, 8)>>>(W1, w1h, w1l, 256, 1024,
                                              (size_t)256 * 1024, (size_t)1024 * 256);// 3
    prep_w<<<dim3(8, 32, NL_), dim3(32, 8)>>>(W2, w2h, w2l, 1024, 256,
                                              (size_t)1024 * 256, (size_t)256 * 1024);// 4
    const int n2 = NTOK * C_ / 2;
    add0_bias<<<(n2 + 255) / 256, 256>>>(src, pos, xpH, xpL, n2, bv, boff, bat, bcat);// 5

    dim3 gcat(640 / 128, NTOK / 128);    // (5, 340)
    dim3 g256(256 / 128, NTOK / 128);    // (2, 340)
    dim3 g1024(1024 / 128, NTOK / 128);  // (8, 340)

    for (int i = 0; i < NL_; i++) {
        // fused projection: v (fp16) + off/att (fp32)        <- launch #6 on i==0
        gemm_mma<2><<<gcat, 512, shm>>>(xpH, xpL,
                                        wch + (size_t)i * 640 * 256, wcl + (size_t)i * 640 * 256,
                                        bcat + i * 640, nullptr, vh, oa, nullptr, nullptr,
                                        NTOK, 256, 640);
        // sampling (softmax inlined), split output
        deform_sample<<<NTOK, 256>>>(vh, oa, ref, aoH, aoL);
        // output projection + LN1
        gemm_mma<0><<<g256, 512, shm>>>(aoH, aoL,
                                        woh + (size_t)i * 256 * 256, wol + (size_t)i * 256 * 256,
                                        bo + i * 256, tmp, nullptr, nullptr, nullptr, nullptr,
                                        NTOK, 256, 256);
        ln_kernel<<<NTOK / 8, 256>>>(xpH, xpL, tmp, n1s + i * 256, n1b + i * 256,
                                     nullptr, xH, xL, nullptr);
        // FFN + LN2 (fused +pos -> next xp)
        gemm_mma<1><<<g1024, 512, shm>>>(xH, xL,
                                         w1h + (size_t)i * 1024 * 256, w1l + (size_t)i * 1024 * 256,
                                         b1 + i * 1024, nullptr, nullptr, nullptr, hH, hL,
                                         NTOK, 256, 1024);
        gemm_mma<0><<<g256, 512, shm>>>(hH, hL,
                                        w2h + (size_t)i * 256 * 1024, w2l + (size_t)i * 256 * 1024,
                                        b2 + i * 256, tmp, nullptr, nullptr, nullptr, nullptr,
                                        NTOK, 1024, 256);
        bool last = (i == NL_ - 1);
        ln_kernel<<<NTOK / 8, 256>>>(xH, xL, tmp, n2s + i * 256, n2b + i * 256,
                                     last ? nullptr : pos,
                                     last ? nullptr : xpH, last ? nullptr : xpL,
                                     last ? (float*)d_out : nullptr);
    }
}

// round 13
// speedup vs baseline: 1.7098x; 1.2321x over previous
#include <cuda_runtime.h>
#include <cuda_bf16.h>
#include <cuda_fp16.h>
#include <math.h>
#include <stdint.h>

// Problem constants
#define NTOK  43520        // B * LQ
#define LQ_   21760
#define C_    256
#define NHEAD_ 8
#define FF_   1024
#define NL_   6

// ---------------------------------------------------------------------------
// Scratch (static device allocations; no cudaMalloc anywhere)
// Activations stored as EXACT fp16 hi/lo plane pairs (A = H + L, err ~2^-22).
// Weights stored as single rounded fp16 plane (err ~2^-12, the only lossy step).
// ---------------------------------------------------------------------------
__device__ __align__(16) __half g_xpH[NTOK * C_], g_xpL[NTOK * C_];
__device__ __align__(16) __half g_xH [NTOK * C_], g_xL [NTOK * C_];
__device__ __align__(16) __half g_aoH[NTOK * C_], g_aoL[NTOK * C_];
__device__ __align__(16) __half g_hH [NTOK * FF_], g_hL [NTOK * FF_];
__device__ float  g_tmp[NTOK * C_];
__device__ __half g_vh [NTOK * C_];        // value proj, fp16 (gather source)
__device__ float  g_oa [NTOK * 384];       // off (256) + att logits (128), fused

// fp16 weights, all layers: [N,K]
__device__ __align__(16) __half g_wcat[NL_ * 640 * 256];
__device__ __align__(16) __half g_wo  [NL_ * 256 * 256];
__device__ __align__(16) __half g_w1  [NL_ * 1024 * 256];
__device__ __align__(16) __half g_w2  [NL_ * 256 * 1024];
__device__ float g_bcat[NL_ * 640];

// ---------------------------------------------------------------------------
// PTX helpers (sm_103 base target)
// ---------------------------------------------------------------------------
__device__ __forceinline__ uint32_t smem_u32(const void* p) {
    return (uint32_t)__cvta_generic_to_shared(p);
}
__device__ __forceinline__ void cp_async16(uint32_t saddr, const void* gaddr) {
    asm volatile("cp.async.cg.shared.global [%0], [%1], 16;" :: "r"(saddr), "l"(gaddr));
}
__device__ __forceinline__ void cp_commit() {
    asm volatile("cp.async.commit_group;" ::: "memory");
}
__device__ __forceinline__ void cp_wait0() {
    asm volatile("cp.async.wait_group 0;" ::: "memory");
}
__device__ __forceinline__ void ldsm4(uint32_t* r, uint32_t a) {
    asm volatile("ldmatrix.sync.aligned.m8n8.x4.shared.b16 {%0,%1,%2,%3}, [%4];"
                 : "=r"(r[0]), "=r"(r[1]), "=r"(r[2]), "=r"(r[3]) : "r"(a));
}
__device__ __forceinline__ void mma16816(float* c, const uint32_t* a, const uint32_t* b) {
    asm volatile("mma.sync.aligned.m16n8k16.row.col.f32.f16.f16.f32 "
                 "{%0,%1,%2,%3}, {%4,%5,%6,%7}, {%8,%9}, {%0,%1,%2,%3};"
                 : "+f"(c[0]), "+f"(c[1]), "+f"(c[2]), "+f"(c[3])
                 : "r"(a[0]), "r"(a[1]), "r"(a[2]), "r"(a[3]), "r"(b[0]), "r"(b[1]));
}
__device__ __forceinline__ void split2h(float v, __half& h, __half& l) {
    h = __float2half_rn(v);
    l = __float2half_rn(v - __half2float(h));
}

// ---------------------------------------------------------------------------
// Weight prep: W fp32 [K,N] slice -> fp16 [N,K] (transpose + round)
// ---------------------------------------------------------------------------
__global__ void prep_w(const float* __restrict__ W, __half* __restrict__ Bh,
                       int K, int N, size_t srcLayerStride, size_t dstLayerStride) {
    const int L = blockIdx.z;
    W  += (size_t)L * srcLayerStride;
    Bh += (size_t)L * dstLayerStride;
    __shared__ float t[32][33];
    int k0 = blockIdx.y * 32, n0 = blockIdx.x * 32;
    for (int i = threadIdx.y; i < 32; i += 8)
        t[i][threadIdx.x] = W[(size_t)(k0 + i) * N + n0 + threadIdx.x];
    __syncthreads();
    for (int i = threadIdx.y; i < 32; i += 8)
        Bh[(size_t)(n0 + i) * K + k0 + threadIdx.x] = __float2half_rn(t[threadIdx.x][i]);
}

// Concatenated projection-weight prep: [Wv | Woff | Wat] -> [640,256] per layer
__global__ void prep_cat(const float* __restrict__ Wv, const float* __restrict__ Woff,
                         const float* __restrict__ Wat, __half* __restrict__ Bh) {
    const int L = blockIdx.z;
    const int n0 = blockIdx.x * 32;
    const int k0 = blockIdx.y * 32;
    const float* W;
    int srcN, ncol;
    if (n0 < 256)      { W = Wv   + (size_t)L * 256 * 256; srcN = 256; ncol = n0; }
    else if (n0 < 512) { W = Woff + (size_t)L * 256 * 256; srcN = 256; ncol = n0 - 256; }
    else               { W = Wat  + (size_t)L * 256 * 128; srcN = 128; ncol = n0 - 512; }
    Bh += (size_t)L * 640 * 256;
    __shared__ float t[32][33];
    for (int i = threadIdx.y; i < 32; i += 8)
        t[i][threadIdx.x] = W[(size_t)(k0 + i) * srcN + ncol + threadIdx.x];
    __syncthreads();
    for (int i = threadIdx.y; i < 32; i += 8)
        Bh[(size_t)(n0 + i) * 256 + k0 + threadIdx.x] = __float2half_rn(t[threadIdx.x][i]);
}

// fused: xp0 = fp16-split(src + pos) AND bias concat
__global__ void add0_bias(const float* __restrict__ a, const float* __restrict__ b,
                          __half* __restrict__ oh, __half* __restrict__ ol, int n2,
                          const float* __restrict__ bv, const float* __restrict__ boff,
                          const float* __restrict__ bat, float* __restrict__ bcat) {
    int i = blockIdx.x * blockDim.x + threadIdx.x;
    if (i < NL_ * 640) {
        int L = i / 640, c = i % 640;
        float v;
        if (c < 256)      v = bv  [L * 256 + c];
        else if (c < 512) v = boff[L * 256 + c - 256];
        else              v = bat [L * 128 + c - 512];
        bcat[i] = v;
    }
    if (i >= n2) return;
    float2 av = reinterpret_cast<const float2*>(a)[i];
    float2 bv2 = reinterpret_cast<const float2*>(b)[i];
    float v0 = av.x + bv2.x, v1 = av.y + bv2.y;
    __half h0, l0, h1, l1;
    split2h(v0, h0, l0); split2h(v1, h1, l1);
    reinterpret_cast<__half2*>(oh)[i] = __halves2half2(h0, h1);
    reinterpret_cast<__half2*>(ol)[i] = __halves2half2(l0, l1);
}

// ---------------------------------------------------------------------------
// 2-product fp16 HMMA GEMM: C[M,N] = (Ah+Al)[M,K] @ B[N,K]^T + bias
// A exact fp16 split, B rounded fp16. 2 MMAs/tile into one fp32 accumulator.
// CTA tile 128x128, BK=32, 256 threads (8 warps 2x4; warp tile 64x32), 2-stage.
// MODE 0: fp32 out. MODE 1: ReLU + fp16-split out (OH/OL).
// MODE 2: fused projection (N=640): col<256 -> fp16 VH; col>=256 -> fp32 OA.
// ---------------------------------------------------------------------------
#define OFF_AH 0
#define OFF_AL 10240
#define OFF_B  20480
#define STAGE_BYTES 30720

template <int MODE>
__global__ __launch_bounds__(256) void gemm_mma(
        const __half* __restrict__ Ah, const __half* __restrict__ Al,
        const __half* __restrict__ B,
        const float* __restrict__ bias,
        float* __restrict__ C, __half* __restrict__ VH, float* __restrict__ OA,
        __half* __restrict__ OH, __half* __restrict__ OL,
        int M, int K, int N_) {
    extern __shared__ char smem[];
    const uint32_t sbase = smem_u32(smem);
    const int tid  = threadIdx.x;
    const int wid  = tid >> 5;
    const int lane = tid & 31;
    const int warpM = wid >> 2;          // 0..1 -> M offset *64
    const int warpN = wid & 3;           // 0..3 -> N offset *32
    const int m0 = blockIdx.y * 128;
    const int n0 = blockIdx.x * 128;

    float acc[4][4][4];
    #pragma unroll
    for (int i = 0; i < 4; i++)
        #pragma unroll
        for (int j = 0; j < 4; j++)
            #pragma unroll
            for (int r = 0; r < 4; r++) acc[i][j][r] = 0.f;

    const int nkt = K >> 5;

    auto loadAB = [&](int kt, uint32_t stage_u) {
        #pragma unroll
        for (int i = 0; i < 2; i++) {
            int idx = tid + i * 256;              // 0..511
            int row = idx >> 2;                   // 0..127
            int ch  = (idx & 3) << 3;             // 0,8,16,24 (halves)
            size_t ga = (size_t)(m0 + row) * K + kt * 32 + ch;
            size_t gb = (size_t)(n0 + row) * K + kt * 32 + ch;
            uint32_t s = stage_u + row * 80 + ch * 2;
            cp_async16(s + OFF_AH, Ah + ga);
            cp_async16(s + OFF_AL, Al + ga);
            cp_async16(s + OFF_B,  B  + gb);
        }
    };
    auto compute = [&](uint32_t stage_u) {
        const int ar = lane & 15;
        const int ak = (lane >> 4) << 3;
        const int bn = (lane & 7) + ((lane >> 4) << 3);   // 0..15
        const int bk = ((lane >> 3) & 1) << 3;
        #pragma unroll
        for (int kk = 0; kk < 32; kk += 16) {
            uint32_t bf[4][2];
            #pragma unroll
            for (int j2 = 0; j2 < 2; j2++) {
                uint32_t r[4];
                uint32_t addr = stage_u + OFF_B +
                                (warpN * 32 + j2 * 16 + bn) * 80 + (kk + bk) * 2;
                ldsm4(r, addr);
                bf[j2*2][0]=r[0]; bf[j2*2][1]=r[1]; bf[j2*2+1][0]=r[2]; bf[j2*2+1][1]=r[3];
            }
            #pragma unroll
            for (int i = 0; i < 4; i++) {
                uint32_t ah[4], al[4];
                uint32_t a = stage_u + OFF_AH +
                             (warpM * 64 + i * 16 + ar) * 80 + (kk + ak) * 2;
                ldsm4(ah, a);
                ldsm4(al, a + OFF_AL);
                #pragma unroll
                for (int j = 0; j < 4; j++) {
                    mma16816(acc[i][j], ah, bf[j]);
                    mma16816(acc[i][j], al, bf[j]);
                }
            }
        }
    };

    // prologue
    loadAB(0, sbase);
    cp_commit();
    cp_wait0();
    __syncthreads();

    // main loop (double buffered)
    for (int kt = 0; kt < nkt; kt++) {
        const uint32_t cur = sbase + (uint32_t)(kt & 1) * STAGE_BYTES;
        const uint32_t nxt = sbase + (uint32_t)((kt + 1) & 1) * STAGE_BYTES;
        if (kt + 1 < nkt) {
            loadAB(kt + 1, nxt);
            cp_commit();
        }
        compute(cur);
        if (kt + 1 < nkt) cp_wait0();
        __syncthreads();
    }

    // epilogue
    const int tr = lane >> 2;
    const int tc = (lane & 3) * 2;
    #pragma unroll
    for (int i = 0; i < 4; i++) {
        #pragma unroll
        for (int j = 0; j < 4; j++) {
            int row = m0 + warpM * 64 + i * 16 + tr;
            int col = n0 + warpN * 32 + j * 8 + tc;
            float2 bb = *reinterpret_cast<const float2*>(bias + col);
            float2 o0, o1;
            o0.x = acc[i][j][0] + bb.x; o0.y = acc[i][j][1] + bb.y;
            o1.x = acc[i][j][2] + bb.x; o1.y = acc[i][j][3] + bb.y;
            if (MODE == 1) {
                o0.x = fmaxf(o0.x, 0.f); o0.y = fmaxf(o0.y, 0.f);
                o1.x = fmaxf(o1.x, 0.f); o1.y = fmaxf(o1.y, 0.f);
                __half h0, l0, h1, l1;
                split2h(o0.x, h0, l0); split2h(o0.y, h1, l1);
                *reinterpret_cast<__half2*>(OH + (size_t)row * N_ + col) = __halves2half2(h0, h1);
                *reinterpret_cast<__half2*>(OL + (size_t)row * N_ + col) = __halves2half2(l0, l1);
                split2h(o1.x, h0, l0); split2h(o1.y, h1, l1);
                *reinterpret_cast<__half2*>(OH + (size_t)(row + 8) * N_ + col) = __halves2half2(h0, h1);
                *reinterpret_cast<__half2*>(OL + (size_t)(row + 8) * N_ + col) = __halves2half2(l0, l1);
            } else if (MODE == 2) {
                if (col < 256) {
                    *reinterpret_cast<__half2*>(VH + (size_t)row * 256 + col) =
                        __floats2half2_rn(o0.x, o0.y);
                    *reinterpret_cast<__half2*>(VH + (size_t)(row + 8) * 256 + col) =
                        __floats2half2_rn(o1.x, o1.y);
                } else {
                    int co = col - 256;
                    *reinterpret_cast<float2*>(OA + (size_t)row * 384 + co) = o0;
                    *reinterpret_cast<float2*>(OA + (size_t)(row + 8) * 384 + co) = o1;
                }
            } else {
                *reinterpret_cast<float2*>(C + (size_t)row * N_ + col) = o0;
                *reinterpret_cast<float2*>(C + (size_t)(row + 8) * N_ + col) = o1;
            }
        }
    }
}

// ---------------------------------------------------------------------------
// Deformable sampling with inline softmax; v fp16, off/att fused (stride 384).
// One warp per (token, head); lane = channel. Output fp16 split.
// ---------------------------------------------------------------------------
__global__ void deform_sample(const __half* __restrict__ vh,
                              const float* __restrict__ oa,
                              const float* __restrict__ ref,
                              __half* __restrict__ outH,
                              __half* __restrict__ outL) {
    int w = blockIdx.x * 8 + (threadIdx.x >> 5);
    if (w >= NTOK * NHEAD_) return;
    int lane = threadIdx.x & 31;
    int h = w & 7;
    int t = w >> 3;
    int b = t / LQ_;

    float rx = ref[t * 2 + 0];
    float ry = ref[t * 2 + 1];
    const float* op = oa + (size_t)t * 384 + h * 32;
    const float* lp = oa + (size_t)t * 384 + 256 + h * 16;

    float e[16];
    float m = -1e30f;
    #pragma unroll
    for (int j = 0; j < 16; j++) { e[j] = lp[j]; m = fmaxf(m, e[j]); }
    float s = 0.f;
    #pragma unroll
    for (int j = 0; j < 16; j++) { e[j] = expf(e[j] - m); s += e[j]; }
    float inv = 1.f / s;

    const int Ws[4]     = {128, 64, 32, 16};
    const int starts[4] = {0, 16384, 20480, 21504};

    float acc = 0.f;
    #pragma unroll
    for (int l = 0; l < 4; l++) {
        const int   W    = Ws[l];
        const float invW = 1.f / (float)W;
        const float Wm1  = (float)(W - 1);
        const __half* vb = vh + ((size_t)(b * LQ_ + starts[l])) * 256 + h * 32 + lane;
        #pragma unroll
        for (int k = 0; k < 4; k++) {
            float ox  = op[l * 8 + k * 2 + 0];
            float oy  = op[l * 8 + k * 2 + 1];
            float wgt = e[l * 4 + k] * inv;
            float x = (rx + ox * invW) * Wm1;
            float y = (ry + oy * invW) * Wm1;
            x = fminf(fmaxf(x, 0.f), Wm1);
            y = fminf(fmaxf(y, 0.f), Wm1);
            float x0f = floorf(x), y0f = floorf(y);
            float wx = x - x0f, wy = y - y0f;
            int x0 = (int)x0f, y0 = (int)y0f;
            int x1 = min(x0 + 1, W - 1);
            int y1 = min(y0 + 1, W - 1);
            const __half* r0 = vb + (size_t)(y0 * W) * 256;
            const __half* r1 = vb + (size_t)(y1 * W) * 256;
            float v00 = __half2float(r0[x0 * 256]);
            float v10 = __half2float(r0[x1 * 256]);
            float v01 = __half2float(r1[x0 * 256]);
            float v11 = __half2float(r1[x1 * 256]);
            float top = v00 + wx * (v10 - v00);
            float bot = v01 + wx * (v11 - v01);
            acc += wgt * (top + wy * (bot - top));
        }
    }
    __half hh, ll;
    split2h(acc, hh, ll);
    outH[(size_t)t * 256 + h * 32 + lane] = hh;
    outL[(size_t)t * 256 + h * 32 + lane] = ll;
}

// ---------------------------------------------------------------------------
// LayerNorm( (aH+aL) + b ) over C=256, one warp per row.
// Writes fp16 split of (result [+ pos]) to outH/outL, or fp32 to out32.
// ---------------------------------------------------------------------------
__global__ void ln_kernel(const __half* __restrict__ aH,
                          const __half* __restrict__ aL,
                          const float* __restrict__ b,
                          const float* __restrict__ gm, const float* __restrict__ bt,
                          const float* __restrict__ pos,
                          __half* __restrict__ outH, __half* __restrict__ outL,
                          float* __restrict__ out32) {
    int row = blockIdx.x * 8 + (threadIdx.x >> 5);
    if (row >= NTOK) return;
    int lane = threadIdx.x & 31;
    const __half* ah = aH + (size_t)row * 256;
    const __half* al = aL + (size_t)row * 256;
    const float* bp = b + (size_t)row * 256;

    float vals[8];
    float s = 0.f;
    #pragma unroll
    for (int i = 0; i < 8; i++) {
        int c = lane + i * 32;
        vals[i] = __half2float(ah[c]) + __half2float(al[c]) + bp[c];
        s += vals[i];
    }
    #pragma unroll
    for (int o = 16; o; o >>= 1) s += __shfl_xor_sync(0xffffffffu, s, o);
    float mean = s * (1.f / 256.f);

    float var = 0.f;
    #pragma unroll
    for (int i = 0; i < 8; i++) { float d = vals[i] - mean; var += d * d; }
    #pragma unroll
    for (int o = 16; o; o >>= 1) var += __shfl_xor_sync(0xffffffffu, var, o);
    float rstd = rsqrtf(var * (1.f / 256.f) + 1e-5f);

    #pragma unroll
    for (int i = 0; i < 8; i++) {
        int c = lane + i * 32;
        float r = (vals[i] - mean) * rstd * gm[c] + bt[c];
        if (out32) {
            out32[(size_t)row * 256 + c] = r;
        } else {
            float w = pos ? (r + pos[(size_t)row * 256 + c]) : r;
            __half hh, ll;
            split2h(w, hh, ll);
            outH[(size_t)row * 256 + c] = hh;
            outL[(size_t)row * 256 + c] = ll;
        }
    }
}

// ---------------------------------------------------------------------------
// Launch
// ---------------------------------------------------------------------------
extern "C" void kernel_launch(void* const* d_in, const int* in_sizes, int n_in,
                              void* d_out, int out_size) {
    const float* src  = (const float*)d_in[0];
    const float* pos  = (const float*)d_in[1];
    const float* ref  = (const float*)d_in[2];
    const float* Woff = (const float*)d_in[3];
    const float* boff = (const float*)d_in[4];
    const float* Wat  = (const float*)d_in[5];
    const float* bat  = (const float*)d_in[6];
    const float* Wv   = (const float*)d_in[7];
    const float* bv   = (const float*)d_in[8];
    const float* Wo   = (const float*)d_in[9];
    const float* bo   = (const float*)d_in[10];
    const float* W1   = (const float*)d_in[11];
    const float* b1   = (const float*)d_in[12];
    const float* W2   = (const float*)d_in[13];
    const float* b2   = (const float*)d_in[14];
    const float* n1s  = (const float*)d_in[15];
    const float* n1b  = (const float*)d_in[16];
    const float* n2s  = (const float*)d_in[17];
    const float* n2b  = (const float*)d_in[18];

    __half *xpH, *xpL, *xH, *xL, *aoH, *aoL, *hH, *hL, *vh;
    float *tmp, *oa, *bcat;
    __half *wc, *wo, *w1, *w2;
    cudaGetSymbolAddress((void**)&xpH, g_xpH); cudaGetSymbolAddress((void**)&xpL, g_xpL);
    cudaGetSymbolAddress((void**)&xH,  g_xH);  cudaGetSymbolAddress((void**)&xL,  g_xL);
    cudaGetSymbolAddress((void**)&aoH, g_aoH); cudaGetSymbolAddress((void**)&aoL, g_aoL);
    cudaGetSymbolAddress((void**)&hH,  g_hH);  cudaGetSymbolAddress((void**)&hL,  g_hL);
    cudaGetSymbolAddress((void**)&tmp,  g_tmp);
    cudaGetSymbolAddress((void**)&vh,   g_vh);
    cudaGetSymbolAddress((void**)&oa,   g_oa);
    cudaGetSymbolAddress((void**)&bcat, g_bcat);
    cudaGetSymbolAddress((void**)&wc,   g_wcat);
    cudaGetSymbolAddress((void**)&wo,   g_wo);
    cudaGetSymbolAddress((void**)&w1,   g_w1);
    cudaGetSymbolAddress((void**)&w2,   g_w2);

    size_t shm = 2 * STAGE_BYTES;   // 61440
    cudaFuncSetAttribute(gemm_mma<0>, cudaFuncAttributeMaxDynamicSharedMemorySize, (int)shm);
    cudaFuncSetAttribute(gemm_mma<1>, cudaFuncAttributeMaxDynamicSharedMemorySize, (int)shm);
    cudaFuncSetAttribute(gemm_mma<2>, cudaFuncAttributeMaxDynamicSharedMemorySize, (int)shm);

    // ---- one-time weight prep ----
    prep_cat<<<dim3(20, 8, NL_), dim3(32, 8)>>>(Wv, Woff, Wat, wc);
    prep_w<<<dim3(8, 8, NL_),  dim3(32, 8)>>>(Wo, wo, 256, 256,
                                              (size_t)256 * 256,  (size_t)256 * 256);
    prep_w<<<dim3(32, 8, NL_), dim3(32, 8)>>>(W1, w1, 256, 1024,
                                              (size_t)256 * 1024, (size_t)1024 * 256);
    prep_w<<<dim3(8, 32, NL_), dim3(32, 8)>>>(W2, w2, 1024, 256,
                                              (size_t)1024 * 256, (size_t)256 * 1024);
    const int n2 = NTOK * C_ / 2;
    add0_bias<<<(n2 + 255) / 256, 256>>>(src, pos, xpH, xpL, n2, bv, boff, bat, bcat);

    dim3 gcat(640 / 128, NTOK / 128);    // (5, 340)
    dim3 g256(256 / 128, NTOK / 128);    // (2, 340)
    dim3 g1024(1024 / 128, NTOK / 128);  // (8, 340)

    for (int i = 0; i < NL_; i++) {
        // fused projection: v (fp16) + off/att (fp32)
        gemm_mma<2><<<gcat, 256, shm>>>(xpH, xpL, wc + (size_t)i * 640 * 256,
                                        bcat + i * 640, nullptr, vh, oa, nullptr, nullptr,
                                        NTOK, 256, 640);
        // sampling (softmax inlined), fp16-split output
        deform_sample<<<NTOK, 256>>>(vh, oa, ref, aoH, aoL);
        // output projection + LN1
        gemm_mma<0><<<g256, 256, shm>>>(aoH, aoL, wo + (size_t)i * 256 * 256,
                                        bo + i * 256, tmp, nullptr, nullptr, nullptr, nullptr,
                                        NTOK, 256, 256);
        ln_kernel<<<NTOK / 8, 256>>>(xpH, xpL, tmp, n1s + i * 256, n1b + i * 256,
                                     nullptr, xH, xL, nullptr);
        // FFN + LN2 (fused +pos -> next xp)
        gemm_mma<1><<<g1024, 256, shm>>>(xH, xL, w1 + (size_t)i * 1024 * 256,
                                         b1 + i * 1024, nullptr, nullptr, nullptr, hH, hL,
                                         NTOK, 256, 1024);
        gemm_mma<0><<<g256, 256, shm>>>(hH, hL, w2 + (size_t)i * 256 * 1024,
                                        b2 + i * 256, tmp, nullptr, nullptr, nullptr, nullptr,
                                        NTOK, 1024, 256);
        bool last = (i == NL_ - 1);
        ln_kernel<<<NTOK / 8, 256>>>(xH, xL, tmp, n2s + i * 256, n2b + i * 256,
                                     last ? nullptr : pos,
                                     last ? nullptr : xpH, last ? nullptr : xpL,
                                     last ? (float*)d_out : nullptr);
    }
}

// round 16
// speedup vs baseline: 1.8885x; 1.1045x over previous
#include <cuda_runtime.h>
#include <cuda_bf16.h>
#include <cuda_fp16.h>
#include <math.h>
#include <stdint.h>

// Problem constants
#define NTOK  43520        // B * LQ
#define LQ_   21760
#define C_    256
#define NHEAD_ 8
#define FF_   1024
#define NL_   6

// ---------------------------------------------------------------------------
// Scratch (static device allocations; no cudaMalloc anywhere)
// Residual-stream activations: EXACT fp16 hi/lo plane pairs (A = H + L).
// h (FFN hidden): single rounded fp16 plane (error budget analysis in R14 notes).
// ---------------------------------------------------------------------------
__device__ __align__(16) __half g_xpH[NTOK * C_], g_xpL[NTOK * C_];
__device__ __align__(16) __half g_xH [NTOK * C_], g_xL [NTOK * C_];
__device__ __align__(16) __half g_aoH[NTOK * C_], g_aoL[NTOK * C_];
__device__ __align__(16) __half g_hH [NTOK * FF_];
__device__ float  g_tmp[NTOK * C_];
__device__ __half g_vh [NTOK * C_];        // value proj, fp16 (gather source)
__device__ float  g_oa [NTOK * 384];       // off (256) + att logits (128), fused

// fp16 weights, all layers: [N,K]
__device__ __align__(16) __half g_wcat[NL_ * 640 * 256];
__device__ __align__(16) __half g_wo  [NL_ * 256 * 256];
__device__ __align__(16) __half g_w1  [NL_ * 1024 * 256];
__device__ __align__(16) __half g_w2  [NL_ * 256 * 1024];
__device__ float g_bcat[NL_ * 640];

// ---------------------------------------------------------------------------
// PTX helpers (sm_103 base target)
// ---------------------------------------------------------------------------
__device__ __forceinline__ uint32_t smem_u32(const void* p) {
    return (uint32_t)__cvta_generic_to_shared(p);
}
__device__ __forceinline__ void cp_async16(uint32_t saddr, const void* gaddr) {
    asm volatile("cp.async.cg.shared.global [%0], [%1], 16;" :: "r"(saddr), "l"(gaddr));
}
__device__ __forceinline__ void cp_commit() {
    asm volatile("cp.async.commit_group;" ::: "memory");
}
__device__ __forceinline__ void cp_wait0() {
    asm volatile("cp.async.wait_group 0;" ::: "memory");
}
__device__ __forceinline__ void ldsm4(uint32_t* r, uint32_t a) {
    asm volatile("ldmatrix.sync.aligned.m8n8.x4.shared.b16 {%0,%1,%2,%3}, [%4];"
                 : "=r"(r[0]), "=r"(r[1]), "=r"(r[2]), "=r"(r[3]) : "r"(a));
}
__device__ __forceinline__ void mma16816(float* c, const uint32_t* a, const uint32_t* b) {
    asm volatile("mma.sync.aligned.m16n8k16.row.col.f32.f16.f16.f32 "
                 "{%0,%1,%2,%3}, {%4,%5,%6,%7}, {%8,%9}, {%0,%1,%2,%3};"
                 : "+f"(c[0]), "+f"(c[1]), "+f"(c[2]), "+f"(c[3])
                 : "r"(a[0]), "r"(a[1]), "r"(a[2]), "r"(a[3]), "r"(b[0]), "r"(b[1]));
}
__device__ __forceinline__ void split2h(float v, __half& h, __half& l) {
    h = __float2half_rn(v);
    l = __float2half_rn(v - __half2float(h));
}

// ---------------------------------------------------------------------------
// Weight prep: W fp32 [K,N] slice -> fp16 [N,K] (transpose + round)
// ---------------------------------------------------------------------------
__global__ void prep_w(const float* __restrict__ W, __half* __restrict__ Bh,
                       int K, int N, size_t srcLayerStride, size_t dstLayerStride) {
    const int L = blockIdx.z;
    W  += (size_t)L * srcLayerStride;
    Bh += (size_t)L * dstLayerStride;
    __shared__ float t[32][33];
    int k0 = blockIdx.y * 32, n0 = blockIdx.x * 32;
    for (int i = threadIdx.y; i < 32; i += 8)
        t[i][threadIdx.x] = W[(size_t)(k0 + i) * N + n0 + threadIdx.x];
    __syncthreads();
    for (int i = threadIdx.y; i < 32; i += 8)
        Bh[(size_t)(n0 + i) * K + k0 + threadIdx.x] = __float2half_rn(t[threadIdx.x][i]);
}

// Concatenated projection-weight prep: [Wv | Woff | Wat] -> [640,256] per layer
__global__ void prep_cat(const float* __restrict__ Wv, const float* __restrict__ Woff,
                         const float* __restrict__ Wat, __half* __restrict__ Bh) {
    const int L = blockIdx.z;
    const int n0 = blockIdx.x * 32;
    const int k0 = blockIdx.y * 32;
    const float* W;
    int srcN, ncol;
    if (n0 < 256)      { W = Wv   + (size_t)L * 256 * 256; srcN = 256; ncol = n0; }
    else if (n0 < 512) { W = Woff + (size_t)L * 256 * 256; srcN = 256; ncol = n0 - 256; }
    else               { W = Wat  + (size_t)L * 256 * 128; srcN = 128; ncol = n0 - 512; }
    Bh += (size_t)L * 640 * 256;
    __shared__ float t[32][33];
    for (int i = threadIdx.y; i < 32; i += 8)
        t[i][threadIdx.x] = W[(size_t)(k0 + i) * srcN + ncol + threadIdx.x];
    __syncthreads();
    for (int i = threadIdx.y; i < 32; i += 8)
        Bh[(size_t)(n0 + i) * 256 + k0 + threadIdx.x] = __float2half_rn(t[threadIdx.x][i]);
}

// fused: xp0 = fp16-split(src + pos) AND bias concat
__global__ void add0_bias(const float* __restrict__ a, const float* __restrict__ b,
                          __half* __restrict__ oh, __half* __restrict__ ol, int n2,
                          const float* __restrict__ bv, const float* __restrict__ boff,
                          const float* __restrict__ bat, float* __restrict__ bcat) {
    int i = blockIdx.x * blockDim.x + threadIdx.x;
    if (i < NL_ * 640) {
        int L = i / 640, c = i % 640;
        float v;
        if (c < 256)      v = bv  [L * 256 + c];
        else if (c < 512) v = boff[L * 256 + c - 256];
        else              v = bat [L * 128 + c - 512];
        bcat[i] = v;
    }
    if (i >= n2) return;
    float2 av = reinterpret_cast<const float2*>(a)[i];
    float2 bv2 = reinterpret_cast<const float2*>(b)[i];
    float v0 = av.x + bv2.x, v1 = av.y + bv2.y;
    __half h0, l0, h1, l1;
    split2h(v0, h0, l0); split2h(v1, h1, l1);
    reinterpret_cast<__half2*>(oh)[i] = __halves2half2(h0, h1);
    reinterpret_cast<__half2*>(ol)[i] = __halves2half2(l0, l1);
}

// ---------------------------------------------------------------------------
// fp16 HMMA GEMM: C[M,N] = (Ah[+Al])[M,K] @ B[N,K]^T + bias
// CTA tile 128x128, BK=32, 256 threads (8 warps 2x4; warp tile 64x32), 2-stage.
// MODE 0: 2-product, fp32 out             (Wo: aoH+aoL)
// MODE 1: 2-product, ReLU + single fp16 out (W1 -> hH)
// MODE 2: fused projection (N=640): v cols (n0<256) 2-product -> fp16 VH;
//         off/att cols (n0>=256) 1-product -> fp32 OA.
// MODE 3: 1-product, fp32 out             (W2: hH only)
// ---------------------------------------------------------------------------
#define OFF_AH 0
#define OFF_AL 10240
#define OFF_B  20480
#define STAGE_BYTES 30720

template <int MODE>
__global__ __launch_bounds__(256) void gemm_mma(
        const __half* __restrict__ Ah, const __half* __restrict__ Al,
        const __half* __restrict__ B,
        const float* __restrict__ bias,
        float* __restrict__ C, __half* __restrict__ VH, float* __restrict__ OA,
        __half* __restrict__ OH,
        int M, int K, int N_) {
    extern __shared__ char smem[];
    const uint32_t sbase = smem_u32(smem);
    const int tid  = threadIdx.x;
    const int wid  = tid >> 5;
    const int lane = tid & 31;
    const int warpM = wid >> 2;          // 0..1 -> M offset *64
    const int warpN = wid & 3;           // 0..3 -> N offset *32
    const int m0 = blockIdx.y * 128;
    const int n0 = blockIdx.x * 128;

    // per-CTA uniform: use the low-plane product?
    const bool useAl = (MODE == 0 || MODE == 1) || (MODE == 2 && n0 < 256);

    float acc[4][4][4];
    #pragma unroll
    for (int i = 0; i < 4; i++)
        #pragma unroll
        for (int j = 0; j < 4; j++)
            #pragma unroll
            for (int r = 0; r < 4; r++) acc[i][j][r] = 0.f;

    const int nkt = K >> 5;

    auto loadAB = [&](int kt, uint32_t stage_u) {
        #pragma unroll
        for (int i = 0; i < 2; i++) {
            int idx = tid + i * 256;              // 0..511
            int row = idx >> 2;                   // 0..127
            int ch  = (idx & 3) << 3;             // 0,8,16,24 (halves)
            size_t ga = (size_t)(m0 + row) * K + kt * 32 + ch;
            size_t gb = (size_t)(n0 + row) * K + kt * 32 + ch;
            uint32_t s = stage_u + row * 80 + ch * 2;
            cp_async16(s + OFF_AH, Ah + ga);
            if (useAl) cp_async16(s + OFF_AL, Al + ga);
            cp_async16(s + OFF_B,  B  + gb);
        }
    };
    auto compute = [&](uint32_t stage_u) {
        const int ar = lane & 15;
        const int ak = (lane >> 4) << 3;
        const int bn = (lane & 7) + ((lane >> 4) << 3);   // 0..15
        const int bk = ((lane >> 3) & 1) << 3;
        #pragma unroll
        for (int kk = 0; kk < 32; kk += 16) {
            uint32_t bf[4][2];
            #pragma unroll
            for (int j2 = 0; j2 < 2; j2++) {
                uint32_t r[4];
                uint32_t addr = stage_u + OFF_B +
                                (warpN * 32 + j2 * 16 + bn) * 80 + (kk + bk) * 2;
                ldsm4(r, addr);
                bf[j2*2][0]=r[0]; bf[j2*2][1]=r[1]; bf[j2*2+1][0]=r[2]; bf[j2*2+1][1]=r[3];
            }
            #pragma unroll
            for (int i = 0; i < 4; i++) {
                uint32_t ah[4], al[4];
                uint32_t a = stage_u + OFF_AH +
                             (warpM * 64 + i * 16 + ar) * 80 + (kk + ak) * 2;
                ldsm4(ah, a);
                if (useAl) ldsm4(al, a + OFF_AL);
                #pragma unroll
                for (int j = 0; j < 4; j++) {
                    mma16816(acc[i][j], ah, bf[j]);
                    if (useAl) mma16816(acc[i][j], al, bf[j]);
                }
            }
        }
    };

    // prologue
    loadAB(0, sbase);
    cp_commit();
    cp_wait0();
    __syncthreads();

    // main loop (double buffered)
    for (int kt = 0; kt < nkt; kt++) {
        const uint32_t cur = sbase + (uint32_t)(kt & 1) * STAGE_BYTES;
        const uint32_t nxt = sbase + (uint32_t)((kt + 1) & 1) * STAGE_BYTES;
        if (kt + 1 < nkt) {
            loadAB(kt + 1, nxt);
            cp_commit();
        }
        compute(cur);
        if (kt + 1 < nkt) cp_wait0();
        __syncthreads();
    }

    // epilogue
    const int tr = lane >> 2;
    const int tc = (lane & 3) * 2;
    #pragma unroll
    for (int i = 0; i < 4; i++) {
        #pragma unroll
        for (int j = 0; j < 4; j++) {
            int row = m0 + warpM * 64 + i * 16 + tr;
            int col = n0 + warpN * 32 + j * 8 + tc;
            float2 bb = *reinterpret_cast<const float2*>(bias + col);
            float2 o0, o1;
            o0.x = acc[i][j][0] + bb.x; o0.y = acc[i][j][1] + bb.y;
            o1.x = acc[i][j][2] + bb.x; o1.y = acc[i][j][3] + bb.y;
            if (MODE == 1) {
                o0.x = fmaxf(o0.x, 0.f); o0.y = fmaxf(o0.y, 0.f);
                o1.x = fmaxf(o1.x, 0.f); o1.y = fmaxf(o1.y, 0.f);
                *reinterpret_cast<__half2*>(OH + (size_t)row * N_ + col) =
                    __floats2half2_rn(o0.x, o0.y);
                *reinterpret_cast<__half2*>(OH + (size_t)(row + 8) * N_ + col) =
                    __floats2half2_rn(o1.x, o1.y);
            } else if (MODE == 2) {
                if (col < 256) {
                    *reinterpret_cast<__half2*>(VH + (size_t)row * 256 + col) =
                        __floats2half2_rn(o0.x, o0.y);
                    *reinterpret_cast<__half2*>(VH + (size_t)(row + 8) * 256 + col) =
                        __floats2half2_rn(o1.x, o1.y);
                } else {
                    int co = col - 256;
                    *reinterpret_cast<float2*>(OA + (size_t)row * 384 + co) = o0;
                    *reinterpret_cast<float2*>(OA + (size_t)(row + 8) * 384 + co) = o1;
                }
            } else {  // MODE 0 / MODE 3
                *reinterpret_cast<float2*>(C + (size_t)row * N_ + col) = o0;
                *reinterpret_cast<float2*>(C + (size_t)(row + 8) * N_ + col) = o1;
            }
        }
    }
}

// ---------------------------------------------------------------------------
// Deformable sampling with inline softmax; v fp16, off/att fused (stride 384).
// One warp per (token, head); lane = channel. Output fp16 split.
// ---------------------------------------------------------------------------
__global__ void deform_sample(const __half* __restrict__ vh,
                              const float* __restrict__ oa,
                              const float* __restrict__ ref,
                              __half* __restrict__ outH,
                              __half* __restrict__ outL) {
    int w = blockIdx.x * 8 + (threadIdx.x >> 5);
    if (w >= NTOK * NHEAD_) return;
    int lane = threadIdx.x & 31;
    int h = w & 7;
    int t = w >> 3;
    int b = t / LQ_;

    float rx = ref[t * 2 + 0];
    float ry = ref[t * 2 + 1];
    const float* op = oa + (size_t)t * 384 + h * 32;
    const float* lp = oa + (size_t)t * 384 + 256 + h * 16;

    float e[16];
    float m = -1e30f;
    #pragma unroll
    for (int j = 0; j < 16; j++) { e[j] = lp[j]; m = fmaxf(m, e[j]); }
    float s = 0.f;
    #pragma unroll
    for (int j = 0; j < 16; j++) { e[j] = expf(e[j] - m); s += e[j]; }
    float inv = 1.f / s;

    const int Ws[4]     = {128, 64, 32, 16};
    const int starts[4] = {0, 16384, 20480, 21504};

    float acc = 0.f;
    #pragma unroll
    for (int l = 0; l < 4; l++) {
        const int   W    = Ws[l];
        const float invW = 1.f / (float)W;
        const float Wm1  = (float)(W - 1);
        const __half* vb = vh + ((size_t)(b * LQ_ + starts[l])) * 256 + h * 32 + lane;
        #pragma unroll
        for (int k = 0; k < 4; k++) {
            float ox  = op[l * 8 + k * 2 + 0];
            float oy  = op[l * 8 + k * 2 + 1];
            float wgt = e[l * 4 + k] * inv;
            float x = (rx + ox * invW) * Wm1;
            float y = (ry + oy * invW) * Wm1;
            x = fminf(fmaxf(x, 0.f), Wm1);
            y = fminf(fmaxf(y, 0.f), Wm1);
            float x0f = floorf(x), y0f = floorf(y);
            float wx = x - x0f, wy = y - y0f;
            int x0 = (int)x0f, y0 = (int)y0f;
            int x1 = min(x0 + 1, W - 1);
            int y1 = min(y0 + 1, W - 1);
            const __half* r0 = vb + (size_t)(y0 * W) * 256;
            const __half* r1 = vb + (size_t)(y1 * W) * 256;
            float v00 = __half2float(r0[x0 * 256]);
            float v10 = __half2float(r0[x1 * 256]);
            float v01 = __half2float(r1[x0 * 256]);
            float v11 = __half2float(r1[x1 * 256]);
            float top = v00 + wx * (v10 - v00);
            float bot = v01 + wx * (v11 - v01);
            acc += wgt * (top + wy * (bot - top));
        }
    }
    __half hh, ll;
    split2h(acc, hh, ll);
    outH[(size_t)t * 256 + h * 32 + lane] = hh;
    outL[(size_t)t * 256 + h * 32 + lane] = ll;
}

// ---------------------------------------------------------------------------
// LayerNorm( (aH+aL) + b ) over C=256, one warp per row.
// Writes fp16 split of (result [+ pos]) to outH/outL, or fp32 to out32.
// ---------------------------------------------------------------------------
__global__ void ln_kernel(const __half* __restrict__ aH,
                          const __half* __restrict__ aL,
                          const float* __restrict__ b,
                          const float* __restrict__ gm, const float* __restrict__ bt,
                          const float* __restrict__ pos,
                          __half* __restrict__ outH, __half* __restrict__ outL,
                          float* __restrict__ out32) {
    int row = blockIdx.x * 8 + (threadIdx.x >> 5);
    if (row >= NTOK) return;
    int lane = threadIdx.x & 31;
    const __half* ah = aH + (size_t)row * 256;
    const __half* al = aL + (size_t)row * 256;
    const float* bp = b + (size_t)row * 256;

    float vals[8];
    float s = 0.f;
    #pragma unroll
    for (int i = 0; i < 8; i++) {
        int c = lane + i * 32;
        vals[i] = __half2float(ah[c]) + __half2float(al[c]) + bp[c];
        s += vals[i];
    }
    #pragma unroll
    for (int o = 16; o; o >>= 1) s += __shfl_xor_sync(0xffffffffu, s, o);
    float mean = s * (1.f / 256.f);

    float var = 0.f;
    #pragma unroll
    for (int i = 0; i < 8; i++) { float d = vals[i] - mean; var += d * d; }
    #pragma unroll
    for (int o = 16; o; o >>= 1) var += __shfl_xor_sync(0xffffffffu, var, o);
    float rstd = rsqrtf(var * (1.f / 256.f) + 1e-5f);

    #pragma unroll
    for (int i = 0; i < 8; i++) {
        int c = lane + i * 32;
        float r = (vals[i] - mean) * rstd * gm[c] + bt[c];
        if (out32) {
            out32[(size_t)row * 256 + c] = r;
        } else {
            float w = pos ? (r + pos[(size_t)row * 256 + c]) : r;
            __half hh, ll;
            split2h(w, hh, ll);
            outH[(size_t)row * 256 + c] = hh;
            outL[(size_t)row * 256 + c] = ll;
        }
    }
}

// ---------------------------------------------------------------------------
// Launch
// ---------------------------------------------------------------------------
extern "C" void kernel_launch(void* const* d_in, const int* in_sizes, int n_in,
                              void* d_out, int out_size) {
    const float* src  = (const float*)d_in[0];
    const float* pos  = (const float*)d_in[1];
    const float* ref  = (const float*)d_in[2];
    const float* Woff = (const float*)d_in[3];
    const float* boff = (const float*)d_in[4];
    const float* Wat  = (const float*)d_in[5];
    const float* bat  = (const float*)d_in[6];
    const float* Wv   = (const float*)d_in[7];
    const float* bv   = (const float*)d_in[8];
    const float* Wo   = (const float*)d_in[9];
    const float* bo   = (const float*)d_in[10];
    const float* W1   = (const float*)d_in[11];
    const float* b1   = (const float*)d_in[12];
    const float* W2   = (const float*)d_in[13];
    const float* b2   = (const float*)d_in[14];
    const float* n1s  = (const float*)d_in[15];
    const float* n1b  = (const float*)d_in[16];
    const float* n2s  = (const float*)d_in[17];
    const float* n2b  = (const float*)d_in[18];

    __half *xpH, *xpL, *xH, *xL, *aoH, *aoL, *hH, *vh;
    float *tmp, *oa, *bcat;
    __half *wc, *wo, *w1, *w2;
    cudaGetSymbolAddress((void**)&xpH, g_xpH); cudaGetSymbolAddress((void**)&xpL, g_xpL);
    cudaGetSymbolAddress((void**)&xH,  g_xH);  cudaGetSymbolAddress((void**)&xL,  g_xL);
    cudaGetSymbolAddress((void**)&aoH, g_aoH); cudaGetSymbolAddress((void**)&aoL, g_aoL);
    cudaGetSymbolAddress((void**)&hH,  g_hH);
    cudaGetSymbolAddress((void**)&tmp,  g_tmp);
    cudaGetSymbolAddress((void**)&vh,   g_vh);
    cudaGetSymbolAddress((void**)&oa,   g_oa);
    cudaGetSymbolAddress((void**)&bcat, g_bcat);
    cudaGetSymbolAddress((void**)&wc,   g_wcat);
    cudaGetSymbolAddress((void**)&wo,   g_wo);
    cudaGetSymbolAddress((void**)&w1,   g_w1);
    cudaGetSymbolAddress((void**)&w2,   g_w2);

    size_t shm = 2 * STAGE_BYTES;   // 61440
    cudaFuncSetAttribute(gemm_mma<0>, cudaFuncAttributeMaxDynamicSharedMemorySize, (int)shm);
    cudaFuncSetAttribute(gemm_mma<1>, cudaFuncAttributeMaxDynamicSharedMemorySize, (int)shm);
    cudaFuncSetAttribute(gemm_mma<2>, cudaFuncAttributeMaxDynamicSharedMemorySize, (int)shm);
    cudaFuncSetAttribute(gemm_mma<3>, cudaFuncAttributeMaxDynamicSharedMemorySize, (int)shm);

    // ---- one-time weight prep ----
    prep_cat<<<dim3(20, 8, NL_), dim3(32, 8)>>>(Wv, Woff, Wat, wc);
    prep_w<<<dim3(8, 8, NL_),  dim3(32, 8)>>>(Wo, wo, 256, 256,
                                              (size_t)256 * 256,  (size_t)256 * 256);
    prep_w<<<dim3(32, 8, NL_), dim3(32, 8)>>>(W1, w1, 256, 1024,
                                              (size_t)256 * 1024, (size_t)1024 * 256);
    prep_w<<<dim3(8, 32, NL_), dim3(32, 8)>>>(W2, w2, 1024, 256,
                                              (size_t)1024 * 256, (size_t)256 * 1024);
    const int n2 = NTOK * C_ / 2;
    add0_bias<<<(n2 + 255) / 256, 256>>>(src, pos, xpH, xpL, n2, bv, boff, bat, bcat);

    dim3 gcat(640 / 128, NTOK / 128);    // (5, 340)
    dim3 g256(256 / 128, NTOK / 128);    // (2, 340)
    dim3 g1024(1024 / 128, NTOK / 128);  // (8, 340)

    for (int i = 0; i < NL_; i++) {
        // fused projection: v (fp16, 2-prod) + off/att (fp32, 1-prod)
        gemm_mma<2><<<gcat, 256, shm>>>(xpH, xpL, wc + (size_t)i * 640 * 256,
                                        bcat + i * 640, nullptr, vh, oa, nullptr,
                                        NTOK, 256, 640);
        // sampling (softmax inlined), fp16-split output
        deform_sample<<<NTOK, 256>>>(vh, oa, ref, aoH, aoL);
        // output projection (2-prod) + LN1
        gemm_mma<0><<<g256, 256, shm>>>(aoH, aoL, wo + (size_t)i * 256 * 256,
                                        bo + i * 256, tmp, nullptr, nullptr, nullptr,
                                        NTOK, 256, 256);
        ln_kernel<<<NTOK / 8, 256>>>(xpH, xpL, tmp, n1s + i * 256, n1b + i * 256,
                                     nullptr, xH, xL, nullptr);
        // FFN: W1 (2-prod, ReLU, single fp16 out) ; W2 (1-prod) + LN2 (+pos)
        gemm_mma<1><<<g1024, 256, shm>>>(xH, xL, w1 + (size_t)i * 1024 * 256,
                                         b1 + i * 1024, nullptr, nullptr, nullptr, hH,
                                         NTOK, 256, 1024);
        gemm_mma<3><<<g256, 256, shm>>>(hH, nullptr, w2 + (size_t)i * 256 * 1024,
                                        b2 + i * 256, tmp, nullptr, nullptr, nullptr,
                                        NTOK, 1024, 256);
        bool last = (i == NL_ - 1);
        ln_kernel<<<NTOK / 8, 256>>>(xH, xL, tmp, n2s + i * 256, n2b + i * 256,
                                     last ? nullptr : pos,
                                     last ? nullptr : xpH, last ? nullptr : xpL,
                                     last ? (float*)d_out : nullptr);
    }
}